// round 6
// baseline (speedup 1.0000x reference)
#include <cuda_runtime.h>
#include <cstdint>
#include <cstddef>

#define B_ 2
#define L_ 512
#define D_ 512
#define H_ 16
#define P_ 128
#define NL_ 2
#define DH_ 32
#define FF_ 2048
#define M_ (B_*L_)

// ------------------------- static device scratch -------------------------
__device__ float g_keep[M_];                      // 1 = keep, 0 = pad
__device__ float g_pfb[(size_t)B_*H_*L_*L_];      // pair bias [b,h,l,m]
__device__ float g_hsum[(size_t)B_*L_*L_];        // sum_h pfb [b,l,m]
__device__ int   g_topk[M_*3];
__device__ float g_f2n[M_*P_];
__device__ float g_cond[M_*D_];
__device__ float g_h[M_*D_];
__device__ float g_hin[M_*D_];
__device__ float g_mod[(size_t)M_*6*D_];
__device__ float g_a[M_*D_];
__device__ float g_qkv[M_*3*D_];
__device__ float g_s[(size_t)B_*H_*L_*L_];
__device__ float g_o[M_*D_];
__device__ float g_hin2[M_*D_];
__device__ float g_m2[M_*D_];
__device__ float g_t[(size_t)M_*FF_];

__device__ __forceinline__ float siluf(float x){ return x * (1.f/(1.f + __expf(-x))); }
__device__ __forceinline__ float geluf(float x){
    return 0.5f*x*(1.f + tanhf(0.79788456080286536f*(x + 0.044715f*x*x*x)));
}

// ------------------------- mask decode -------------------------
// bool mask serialized as int32 (word 1) or float32 (word 0x3f800000):
// nonzero word = pad, zero word = keep.
__global__ void decode_mask_k(const unsigned int* __restrict__ raw) {
    int t = threadIdx.x;                // 1024 threads, one per element
    g_keep[t] = (raw[t] == 0u) ? 1.f : 0.f;
}

// ------------------------- pos embedding -> g_h -------------------------
__global__ void __launch_bounds__(256) pos_emb_k(const float* __restrict__ pos,
                                                 const float* __restrict__ pw) {
    int i = blockIdx.x*256 + threadIdx.x;   // M_*D_
    int row = i >> 9, d = i & 511;
    float v = pos[row*3+0]*pw[d*3+0] + pos[row*3+1]*pw[d*3+1] + pos[row*3+2]*pw[d*3+2];
    g_h[i] = g_keep[row] * v;
}

// ------------------------- pair bias + head-sum -------------------------
// grid (L/32, L, B), 256 thr. pfb[b,h,l,m0..m0+31] + hsum[b,l,m].
__global__ void __launch_bounds__(256) pfb_k(const float* __restrict__ pair,
                                             const float* __restrict__ pfbw) {
    __shared__ float sp[32][129];
    __shared__ float sw[16][128];
    __shared__ float shs[32];
    const int b = blockIdx.z, l = blockIdx.y, m0 = blockIdx.x * 32;
    const int tid = threadIdx.x;
    for (int i = tid; i < 512; i += 256) {
        float4 v = ((const float4*)pfbw)[i];
        int hh = i >> 5, p = (i & 31) * 4;
        sw[hh][p] = v.x; sw[hh][p+1] = v.y; sw[hh][p+2] = v.z; sw[hh][p+3] = v.w;
    }
    if (tid < 32) shs[tid] = 0.f;
    const float* src = pair + (((size_t)(b * L_ + l)) * L_ + m0) * P_;
    for (int i = tid; i < 1024; i += 256) {
        float4 v = ((const float4*)src)[i];
        int mm = i >> 5, p = (i & 31) * 4;
        sp[mm][p]   = siluf(v.x); sp[mm][p+1] = siluf(v.y);
        sp[mm][p+2] = siluf(v.z); sp[mm][p+3] = siluf(v.w);
    }
    __syncthreads();
    const int m = tid & 31, h0 = (tid >> 5) * 2;
    float a0 = 0.f, a1 = 0.f;
    #pragma unroll 16
    for (int p = 0; p < 128; p++) {
        float v = sp[m][p];
        a0 = fmaf(v, sw[h0][p], a0);
        a1 = fmaf(v, sw[h0+1][p], a1);
    }
    size_t base = ((size_t)((b*H_ + h0) * L_ + l)) * L_ + m0 + m;
    g_pfb[base] = a0;
    g_pfb[base + (size_t)L_*L_] = a1;
    atomicAdd(&shs[m], a0 + a1);
    __syncthreads();
    if (tid < 32)
        g_hsum[((size_t)(b*L_ + l))*L_ + m0 + tid] = shs[tid];
}

// ------------------------- top-3 rows per (b, column m) -------------------------
__global__ void __launch_bounds__(256) topk_k() {
    const int warp = threadIdx.x >> 5, lane = threadIdx.x & 31;
    const int bm = blockIdx.x * 8 + warp;
    const int b = bm >> 9, m = bm & 511;
    float lv[3] = {-3.4e38f, -3.4e38f, -3.4e38f};
    int   li[3] = {0x7fffffff, 0x7fffffff, 0x7fffffff};
    for (int l = lane; l < L_; l += 32) {
        float s = g_hsum[((size_t)(b*L_ + l))*L_ + m];
        if (s > lv[0])      { lv[2]=lv[1]; li[2]=li[1]; lv[1]=lv[0]; li[1]=li[0]; lv[0]=s; li[0]=l; }
        else if (s > lv[1]) { lv[2]=lv[1]; li[2]=li[1]; lv[1]=s; li[1]=l; }
        else if (s > lv[2]) { lv[2]=s; li[2]=l; }
    }
    int ptr = 0;
    for (int r = 0; r < 3; r++) {
        float bv = (ptr < 3) ? lv[ptr] : -3.4e38f;
        int   bi = (ptr < 3) ? li[ptr] : 0x7fffffff;
        int   bl = lane;
        #pragma unroll
        for (int o = 16; o; o >>= 1) {
            float ov = __shfl_down_sync(0xffffffffu, bv, o);
            int   oi = __shfl_down_sync(0xffffffffu, bi, o);
            int   ol = __shfl_down_sync(0xffffffffu, bl, o);
            if (ov > bv || (ov == bv && oi < bi)) { bv = ov; bi = oi; bl = ol; }
        }
        bi = __shfl_sync(0xffffffffu, bi, 0);
        bl = __shfl_sync(0xffffffffu, bl, 0);
        if (lane == bl) ptr++;
        if (lane == 0) g_topk[bm*3 + r] = bi;
    }
}

// ------------------------- f2n gather (masked mean of top-3 rows) -------------------------
__global__ void __launch_bounds__(128) f2n_k(const float* __restrict__ pair) {
    const int bm = blockIdx.x;
    const int b = bm >> 9, m = bm & 511;
    const int p = threadIdx.x;
    float acc = 0.f;
    #pragma unroll
    for (int t = 0; t < 3; t++) {
        int l = g_topk[bm*3 + t];
        acc += g_keep[b*L_ + l] * pair[(((size_t)(b*L_ + l))*L_ + m)*P_ + p];
    }
    g_f2n[bm*P_ + p] = acc * g_keep[bm] * (1.f/3.f);
}

// ------------------------- hin = h + time_emb -------------------------
__global__ void __launch_bounds__(256) add_te_k(const float* __restrict__ te) {
    int i = blockIdx.x*256 + threadIdx.x;
    int row = i >> 9;
    int b = row >> 9;
    g_hin[i] = g_h[i] + te[(b << 9) + (i & 511)];
}

// ------------------------- LayerNorm + adaLN modulation -------------------------
__global__ void __launch_bounds__(256) ln_mod_k(const float* __restrict__ in,
                                                const float* __restrict__ mod,
                                                int sh_off, int sc_off,
                                                float* __restrict__ out) {
    const int row = blockIdx.x;
    const float* xr = in + (size_t)row*D_;
    const int t = threadIdx.x;
    float v0 = xr[t], v1 = xr[t+256];
    float s = v0 + v1, q = v0*v0 + v1*v1;
    __shared__ float ss[8], sq[8];
    int lane = t & 31, w = t >> 5;
    #pragma unroll
    for (int o = 16; o; o >>= 1) {
        s += __shfl_down_sync(0xffffffffu, s, o);
        q += __shfl_down_sync(0xffffffffu, q, o);
    }
    if (!lane) { ss[w] = s; sq[w] = q; }
    __syncthreads();
    if (t == 0) {
        float S = 0.f, Q = 0.f;
        #pragma unroll
        for (int i = 0; i < 8; i++) { S += ss[i]; Q += sq[i]; }
        ss[0] = S; sq[0] = Q;
    }
    __syncthreads();
    float mean = ss[0] * (1.f/512.f);
    float var  = sq[0] * (1.f/512.f) - mean*mean;
    float inv  = rsqrtf(var + 1e-5f);
    const float* mrow = mod + (size_t)row*(6*D_);
    out[(size_t)row*D_ + t]       = (v0-mean)*inv*(1.f + mrow[sc_off + t])     + mrow[sh_off + t];
    out[(size_t)row*D_ + t + 256] = (v1-mean)*inv*(1.f + mrow[sc_off + t+256]) + mrow[sh_off + t+256];
}

// ------------------------- generic SGEMM: C = A @ W^T (+bias) + epilogue -------------------------
#define EPI_PLAIN   0
#define EPI_SILU    1
#define EPI_XCOND   2
#define EPI_GELU    3
#define EPI_GATERES 4

template<int BM, int BN, int TM, int TN, int EPI>
__global__ void __launch_bounds__(256)
gemm_k(const float* __restrict__ A, const float* __restrict__ W,
       const float* __restrict__ bias, float* __restrict__ C,
       int K, int N,
       const float* __restrict__ aux,   // XCOND: x [L,B,D]; GATERES: residual [M,D]
       const float* __restrict__ gate)  // GATERES: g_mod + gate offset (row stride 6D)
{
    static_assert((BM/TM)*(BN/TN) == 256, "256 threads");
    __shared__ __align__(16) float As[16][BM];
    __shared__ __align__(16) float Ws[16][BN];
    const int tid = threadIdx.x;
    const int TX = BN / TN;
    const int tx = tid % TX, ty = tid / TX;
    const int m0 = blockIdx.y * BM, n0 = blockIdx.x * BN;

    float acc[TM][TN];
    #pragma unroll
    for (int i = 0; i < TM; i++)
        #pragma unroll
        for (int j = 0; j < TN; j++) acc[i][j] = 0.f;

    for (int k0 = 0; k0 < K; k0 += 16) {
        #pragma unroll
        for (int i = tid; i < BM*4; i += 256) {
            int r = i >> 2, c4 = (i & 3) * 4;
            float4 v = *(const float4*)(A + (size_t)(m0 + r)*K + k0 + c4);
            As[c4+0][r] = v.x; As[c4+1][r] = v.y; As[c4+2][r] = v.z; As[c4+3][r] = v.w;
        }
        #pragma unroll
        for (int i = tid; i < BN*4; i += 256) {
            int r = i >> 2, c4 = (i & 3) * 4;
            float4 v = *(const float4*)(W + (size_t)(n0 + r)*K + k0 + c4);
            Ws[c4+0][r] = v.x; Ws[c4+1][r] = v.y; Ws[c4+2][r] = v.z; Ws[c4+3][r] = v.w;
        }
        __syncthreads();
        #pragma unroll
        for (int k = 0; k < 16; k++) {
            float a[TM], b[TN];
            #pragma unroll
            for (int i = 0; i < TM; i += 4) {
                float4 v = *(const float4*)&As[k][ty*TM + i];
                a[i] = v.x; a[i+1] = v.y; a[i+2] = v.z; a[i+3] = v.w;
            }
            #pragma unroll
            for (int j = 0; j < TN; j += 4) {
                float4 v = *(const float4*)&Ws[k][tx*TN + j];
                b[j] = v.x; b[j+1] = v.y; b[j+2] = v.z; b[j+3] = v.w;
            }
            #pragma unroll
            for (int i = 0; i < TM; i++)
                #pragma unroll
                for (int j = 0; j < TN; j++)
                    acc[i][j] = fmaf(a[i], b[j], acc[i][j]);
        }
        __syncthreads();
    }

    #pragma unroll
    for (int i = 0; i < TM; i++) {
        int gm = m0 + ty*TM + i;
        #pragma unroll
        for (int j = 0; j < TN; j++) {
            int gn = n0 + tx*TN + j;
            float v = acc[i][j];
            if (bias) v += bias[gn];
            float outv;
            if (EPI == EPI_PLAIN) {
                outv = v;
            } else if (EPI == EPI_SILU) {
                outv = siluf(v);
            } else if (EPI == EPI_XCOND) {
                int bb = gm >> 9, ll = gm & 511;
                outv = siluf(aux[((size_t)(ll*B_ + bb))*D_ + gn] + v);
            } else if (EPI == EPI_GELU) {
                outv = geluf(v);
            } else {  // EPI_GATERES (N == D_)
                outv = aux[(size_t)gm*D_ + gn] + gate[(size_t)gm*(6*D_) + gn] * v;
            }
            C[(size_t)gm*N + gn] = outv;
        }
    }
}

// ------------------------- attention scores -------------------------
__global__ void __launch_bounds__(256) attn_scores_k() {
    __shared__ float Qs[64][33];
    __shared__ float Ks[64][33];
    const int bh = blockIdx.z, b = bh >> 4, h = bh & 15;
    const int l0 = blockIdx.y * 64, m0 = blockIdx.x * 64;
    const int tid = threadIdx.x;
    const float* qbase = g_qkv + ((size_t)(b*L_ + l0)) * 1536 + h * 32;
    const float* kbase = g_qkv + ((size_t)(b*L_ + m0)) * 1536 + 512 + h * 32;
    #pragma unroll
    for (int i = tid; i < 512; i += 256) {
        int r = i >> 3, c4 = (i & 7) * 4;
        float4 q4 = *(const float4*)(qbase + (size_t)r * 1536 + c4);
        Qs[r][c4] = q4.x; Qs[r][c4+1] = q4.y; Qs[r][c4+2] = q4.z; Qs[r][c4+3] = q4.w;
        float4 k4 = *(const float4*)(kbase + (size_t)r * 1536 + c4);
        Ks[r][c4] = k4.x; Ks[r][c4+1] = k4.y; Ks[r][c4+2] = k4.z; Ks[r][c4+3] = k4.w;
    }
    __syncthreads();
    const int tx = tid & 15, ty = tid >> 4;
    float acc[4][4] = {};
    #pragma unroll
    for (int k = 0; k < 32; k++) {
        float a[4], bb[4];
        #pragma unroll
        for (int i = 0; i < 4; i++) a[i] = Qs[ty*4 + i][k];
        #pragma unroll
        for (int j = 0; j < 4; j++) bb[j] = Ks[tx*4 + j][k];
        #pragma unroll
        for (int i = 0; i < 4; i++)
            #pragma unroll
            for (int j = 0; j < 4; j++)
                acc[i][j] = fmaf(a[i], bb[j], acc[i][j]);
    }
    const float scale = 0.17677669529663687f;  // 1/sqrt(32)
    #pragma unroll
    for (int i = 0; i < 4; i++) {
        int l = l0 + ty*4 + i;
        size_t srow = ((size_t)(bh*L_ + l)) * L_;
        #pragma unroll
        for (int j = 0; j < 4; j++) {
            int m = m0 + tx*4 + j;
            float v = acc[i][j] * scale + g_pfb[srow + m];
            if (g_keep[b*L_ + m] == 0.f) v = -1e9f;
            g_s[srow + m] = v;
        }
    }
}

// ------------------------- softmax over last dim of g_s -------------------------
__global__ void __launch_bounds__(256) softmax_k() {
    const size_t base = (size_t)blockIdx.x * 512;
    const int t = threadIdx.x;
    float v0 = g_s[base + t], v1 = g_s[base + t + 256];
    __shared__ float red[8];
    __shared__ float red2[8];
    int lane = t & 31, w = t >> 5;
    float m = fmaxf(v0, v1);
    #pragma unroll
    for (int o = 16; o; o >>= 1) m = fmaxf(m, __shfl_down_sync(0xffffffffu, m, o));
    if (!lane) red[w] = m;
    __syncthreads();
    if (t == 0) {
        float M = red[0];
        #pragma unroll
        for (int i = 1; i < 8; i++) M = fmaxf(M, red[i]);
        red[0] = M;
    }
    __syncthreads();
    float M = red[0];
    float e0 = __expf(v0 - M), e1 = __expf(v1 - M);
    float s = e0 + e1;
    #pragma unroll
    for (int o = 16; o; o >>= 1) s += __shfl_down_sync(0xffffffffu, s, o);
    if (!lane) red2[w] = s;
    __syncthreads();
    if (t == 0) {
        float S = 0.f;
        #pragma unroll
        for (int i = 0; i < 8; i++) S += red2[i];
        red2[0] = 1.f / S;
    }
    __syncthreads();
    float inv = red2[0];
    g_s[base + t] = e0 * inv;
    g_s[base + t + 256] = e1 * inv;
}

// ------------------------- O = P @ V -------------------------
__global__ void __launch_bounds__(256) attn_o_k() {
    __shared__ float Ps[64][65];
    __shared__ float Vs[64][33];
    const int bh = blockIdx.y, b = bh >> 4, h = bh & 15;
    const int l0 = blockIdx.x * 64;
    const int tid = threadIdx.x;
    const int tx = tid & 31, ty = tid >> 5;
    float acc[8] = {};
    for (int m0 = 0; m0 < 512; m0 += 64) {
        #pragma unroll
        for (int i = tid; i < 1024; i += 256) {
            int r = i >> 4, c4 = (i & 15) * 4;
            float4 p4 = *(const float4*)(g_s + ((size_t)(bh*L_ + l0 + r))*L_ + m0 + c4);
            Ps[r][c4] = p4.x; Ps[r][c4+1] = p4.y; Ps[r][c4+2] = p4.z; Ps[r][c4+3] = p4.w;
        }
        #pragma unroll
        for (int i = tid; i < 512; i += 256) {
            int r = i >> 3, c4 = (i & 7) * 4;
            float4 v4 = *(const float4*)(g_qkv + ((size_t)(b*L_ + m0 + r))*1536 + 1024 + h*32 + c4);
            Vs[r][c4] = v4.x; Vs[r][c4+1] = v4.y; Vs[r][c4+2] = v4.z; Vs[r][c4+3] = v4.w;
        }
        __syncthreads();
        #pragma unroll 16
        for (int m = 0; m < 64; m++) {
            float v = Vs[m][tx];
            #pragma unroll
            for (int i = 0; i < 8; i++)
                acc[i] = fmaf(Ps[ty + 8*i][m], v, acc[i]);
        }
        __syncthreads();
    }
    #pragma unroll
    for (int i = 0; i < 8; i++) {
        int l = l0 + ty + 8*i;
        g_o[((size_t)(b*L_ + l))*D_ + h*32 + tx] = acc[i];
    }
}

// ------------------------- host launch -------------------------
extern "C" void kernel_launch(void* const* d_in, const int* in_sizes, int n_in,
                              void* d_out, int out_size) {
    const float* x        = (const float*)d_in[0];
    const float* pos      = (const float*)d_in[1];
    const float* time_emb = (const float*)d_in[2];
    const float* pair     = (const float*)d_in[3];
    const float* pos_w    = (const float*)d_in[4];
    const float* pfb_w    = (const float*)d_in[5];
    const float* p2n_w1   = (const float*)d_in[6];
    const float* p2n_w2   = (const float*)d_in[7];
    const float* adaln_w  = (const float*)d_in[8];
    const float* adaln_b  = (const float*)d_in[9];
    const float* qkv_w    = (const float*)d_in[10];
    const float* qkv_b    = (const float*)d_in[11];
    const float* proj_w   = (const float*)d_in[12];
    const float* proj_b   = (const float*)d_in[13];
    const float* mlp_w1   = (const float*)d_in[14];
    const float* mlp_b1   = (const float*)d_in[15];
    const float* mlp_w2   = (const float*)d_in[16];
    const float* mlp_b2   = (const float*)d_in[17];
    const unsigned int* mask = (const unsigned int*)d_in[18];

    float *p_f2n, *p_cond, *p_h, *p_hin, *p_mod, *p_a, *p_qkv, *p_o, *p_hin2, *p_m2, *p_t;
    cudaGetSymbolAddress((void**)&p_f2n,  g_f2n);
    cudaGetSymbolAddress((void**)&p_cond, g_cond);
    cudaGetSymbolAddress((void**)&p_h,    g_h);
    cudaGetSymbolAddress((void**)&p_hin,  g_hin);
    cudaGetSymbolAddress((void**)&p_mod,  g_mod);
    cudaGetSymbolAddress((void**)&p_a,    g_a);
    cudaGetSymbolAddress((void**)&p_qkv,  g_qkv);
    cudaGetSymbolAddress((void**)&p_o,    g_o);
    cudaGetSymbolAddress((void**)&p_hin2, g_hin2);
    cudaGetSymbolAddress((void**)&p_m2,   g_m2);
    cudaGetSymbolAddress((void**)&p_t,    g_t);

    decode_mask_k<<<1, 1024>>>(mask);
    pos_emb_k<<<(M_*D_)/256, 256>>>(pos, pos_w);
    pfb_k<<<dim3(L_/32, L_, B_), 256>>>(pair, pfb_w);
    topk_k<<<M_/8, 256>>>();
    f2n_k<<<M_, 128>>>(pair);

    // pair2node MLP: silu(f2n @ w1^T) @ w2^T ; cond = silu(x + result)
    gemm_k<64,64,4,4,EPI_SILU><<<dim3(P_/64, M_/64), 256>>>(
        p_f2n, p2n_w1, nullptr, p_t, P_, P_, nullptr, nullptr);
    gemm_k<64,64,4,4,EPI_XCOND><<<dim3(D_/64, M_/64), 256>>>(
        p_t, p2n_w2, nullptr, p_cond, P_, D_, x, nullptr);

    for (int l = 0; l < NL_; l++) {
        add_te_k<<<(M_*D_)/256, 256>>>(time_emb);
        // mod = cond @ adaln_w^T + adaln_b  [1024, 3072]
        gemm_k<128,128,8,8,EPI_PLAIN><<<dim3(6*D_/128, M_/128), 256>>>(
            p_cond, adaln_w + (size_t)l*6*D_*D_, adaln_b + (size_t)l*6*D_,
            p_mod, D_, 6*D_, nullptr, nullptr);
        // a = ln(hin)*(1+sc_a)+sh_a
        ln_mod_k<<<M_, 256>>>(p_hin, p_mod, 0, D_, p_a);
        // qkv = a @ qkv_w^T + qkv_b  [1024, 1536]
        gemm_k<128,128,8,8,EPI_PLAIN><<<dim3(3*D_/128, M_/128), 256>>>(
            p_a, qkv_w + (size_t)l*3*D_*D_, qkv_b + (size_t)l*3*D_,
            p_qkv, D_, 3*D_, nullptr, nullptr);
        // attention
        attn_scores_k<<<dim3(L_/64, L_/64, B_*H_), 256>>>();
        softmax_k<<<B_*H_*L_, 256>>>();
        attn_o_k<<<dim3(L_/64, B_*H_), 256>>>();
        // hin2 = hin + g_a * (o @ proj_w^T + proj_b)
        gemm_k<64,64,4,4,EPI_GATERES><<<dim3(D_/64, M_/64), 256>>>(
            p_o, proj_w + (size_t)l*D_*D_, proj_b + (size_t)l*D_,
            p_hin2, D_, D_, p_hin, p_mod + 2*D_);
        // m = ln(hin2)*(1+sc_m)+sh_m
        ln_mod_k<<<M_, 256>>>(p_hin2, p_mod, 3*D_, 4*D_, p_m2);
        // t = gelu(m @ mlp_w1^T + b1)  [1024, 2048]
        gemm_k<128,128,8,8,EPI_GELU><<<dim3(FF_/128, M_/128), 256>>>(
            p_m2, mlp_w1 + (size_t)l*FF_*D_, mlp_b1 + (size_t)l*FF_,
            p_t, D_, FF_, nullptr, nullptr);
        // h = hin2 + g_m * (t @ mlp_w2^T + b2)  -> d_out on last layer
        float* dst = (l == NL_-1) ? (float*)d_out : p_h;
        gemm_k<64,64,4,4,EPI_GATERES><<<dim3(D_/64, M_/64), 256>>>(
            p_t, mlp_w2 + (size_t)l*D_*FF_, mlp_b2 + (size_t)l*D_,
            dst, FF_, D_, p_hin2, p_mod + 5*D_);
    }
    (void)in_sizes; (void)n_in; (void)out_size;
}

// round 7
// speedup vs baseline: 1.0006x; 1.0006x over previous
#include <cuda_runtime.h>
#include <cstdint>
#include <cstddef>

#define B_ 2
#define L_ 512
#define D_ 512
#define H_ 16
#define P_ 128
#define NL_ 2
#define DH_ 32
#define FF_ 2048
#define M_ (B_*L_)

// ------------------------- static device scratch -------------------------
__device__ float g_keep[M_];                      // 1 = keep, 0 = pad
__device__ float g_pfb[(size_t)B_*H_*L_*L_];      // pair bias [b,h,l,m]
__device__ float g_hsum[(size_t)B_*L_*L_];        // sum_h pfb [b,l,m]
__device__ int   g_topk[M_*3];
__device__ float g_f2n[M_*P_];
__device__ float g_cond[M_*D_];
__device__ float g_h[M_*D_];
__device__ float g_hin[M_*D_];
__device__ float g_mod[(size_t)M_*6*D_];
__device__ float g_a[M_*D_];
__device__ float g_qkv[M_*3*D_];
__device__ float g_s[(size_t)B_*H_*L_*L_];
__device__ float g_o[M_*D_];
__device__ float g_hin2[M_*D_];
__device__ float g_m2[M_*D_];
__device__ float g_t[(size_t)M_*FF_];

__device__ __forceinline__ float siluf(float x){ return x * (1.f/(1.f + __expf(-x))); }
__device__ __forceinline__ float geluf(float x){
    return 0.5f*x*(1.f + tanhf(0.79788456080286536f*(x + 0.044715f*x*x*x)));
}

// ------------------------- mask decode -------------------------
// bool mask serialized as int32 (word 1) or float32 (word 0x3f800000):
// nonzero word = pad, zero word = keep.
__global__ void decode_mask_k(const unsigned int* __restrict__ raw) {
    int t = threadIdx.x;                // 1024 threads, one per element
    g_keep[t] = (raw[t] == 0u) ? 1.f : 0.f;
}

// ------------------------- pos embedding -> g_h -------------------------
__global__ void __launch_bounds__(256) pos_emb_k(const float* __restrict__ pos,
                                                 const float* __restrict__ pw) {
    int i = blockIdx.x*256 + threadIdx.x;   // M_*D_
    int row = i >> 9, d = i & 511;
    float v = pos[row*3+0]*pw[d*3+0] + pos[row*3+1]*pw[d*3+1] + pos[row*3+2]*pw[d*3+2];
    g_h[i] = g_keep[row] * v;
}

// ------------------------- pair bias + head-sum -------------------------
// grid (L/32, L, B), 256 thr. pfb[b,h,l,m0..m0+31] + hsum[b,l,m].
__global__ void __launch_bounds__(256) pfb_k(const float* __restrict__ pair,
                                             const float* __restrict__ pfbw) {
    __shared__ float sp[32][129];
    __shared__ float sw[16][128];
    __shared__ float shs[32];
    const int b = blockIdx.z, l = blockIdx.y, m0 = blockIdx.x * 32;
    const int tid = threadIdx.x;
    for (int i = tid; i < 512; i += 256) {
        float4 v = ((const float4*)pfbw)[i];
        int hh = i >> 5, p = (i & 31) * 4;
        sw[hh][p] = v.x; sw[hh][p+1] = v.y; sw[hh][p+2] = v.z; sw[hh][p+3] = v.w;
    }
    if (tid < 32) shs[tid] = 0.f;
    const float* src = pair + (((size_t)(b * L_ + l)) * L_ + m0) * P_;
    for (int i = tid; i < 1024; i += 256) {
        float4 v = ((const float4*)src)[i];
        int mm = i >> 5, p = (i & 31) * 4;
        sp[mm][p]   = siluf(v.x); sp[mm][p+1] = siluf(v.y);
        sp[mm][p+2] = siluf(v.z); sp[mm][p+3] = siluf(v.w);
    }
    __syncthreads();
    const int m = tid & 31, h0 = (tid >> 5) * 2;
    float a0 = 0.f, a1 = 0.f;
    #pragma unroll 16
    for (int p = 0; p < 128; p++) {
        float v = sp[m][p];
        a0 = fmaf(v, sw[h0][p], a0);
        a1 = fmaf(v, sw[h0+1][p], a1);
    }
    size_t base = ((size_t)((b*H_ + h0) * L_ + l)) * L_ + m0 + m;
    g_pfb[base] = a0;
    g_pfb[base + (size_t)L_*L_] = a1;
    atomicAdd(&shs[m], a0 + a1);
    __syncthreads();
    if (tid < 32)
        g_hsum[((size_t)(b*L_ + l))*L_ + m0 + tid] = shs[tid];
}

// ------------------------- top-3 rows per (b, column m) -------------------------
__global__ void __launch_bounds__(256) topk_k() {
    const int warp = threadIdx.x >> 5, lane = threadIdx.x & 31;
    const int bm = blockIdx.x * 8 + warp;
    const int b = bm >> 9, m = bm & 511;
    float lv[3] = {-3.4e38f, -3.4e38f, -3.4e38f};
    int   li[3] = {0x7fffffff, 0x7fffffff, 0x7fffffff};
    for (int l = lane; l < L_; l += 32) {
        float s = g_hsum[((size_t)(b*L_ + l))*L_ + m];
        if (s > lv[0])      { lv[2]=lv[1]; li[2]=li[1]; lv[1]=lv[0]; li[1]=li[0]; lv[0]=s; li[0]=l; }
        else if (s > lv[1]) { lv[2]=lv[1]; li[2]=li[1]; lv[1]=s; li[1]=l; }
        else if (s > lv[2]) { lv[2]=s; li[2]=l; }
    }
    int ptr = 0;
    for (int r = 0; r < 3; r++) {
        float bv = (ptr < 3) ? lv[ptr] : -3.4e38f;
        int   bi = (ptr < 3) ? li[ptr] : 0x7fffffff;
        int   bl = lane;
        #pragma unroll
        for (int o = 16; o; o >>= 1) {
            float ov = __shfl_down_sync(0xffffffffu, bv, o);
            int   oi = __shfl_down_sync(0xffffffffu, bi, o);
            int   ol = __shfl_down_sync(0xffffffffu, bl, o);
            if (ov > bv || (ov == bv && oi < bi)) { bv = ov; bi = oi; bl = ol; }
        }
        bi = __shfl_sync(0xffffffffu, bi, 0);
        bl = __shfl_sync(0xffffffffu, bl, 0);
        if (lane == bl) ptr++;
        if (lane == 0) g_topk[bm*3 + r] = bi;
    }
}

// ------------------------- f2n gather (masked mean of top-3 rows) -------------------------
__global__ void __launch_bounds__(128) f2n_k(const float* __restrict__ pair) {
    const int bm = blockIdx.x;
    const int b = bm >> 9, m = bm & 511;
    const int p = threadIdx.x;
    float acc = 0.f;
    #pragma unroll
    for (int t = 0; t < 3; t++) {
        int l = g_topk[bm*3 + t];
        acc += g_keep[b*L_ + l] * pair[(((size_t)(b*L_ + l))*L_ + m)*P_ + p];
    }
    g_f2n[bm*P_ + p] = acc * g_keep[bm] * (1.f/3.f);
}

// ------------------------- hin = h + time_emb -------------------------
__global__ void __launch_bounds__(256) add_te_k(const float* __restrict__ te) {
    int i = blockIdx.x*256 + threadIdx.x;
    int row = i >> 9;
    int b = row >> 9;
    g_hin[i] = g_h[i] + te[(b << 9) + (i & 511)];
}

// ------------------------- LayerNorm + adaLN modulation -------------------------
__global__ void __launch_bounds__(256) ln_mod_k(const float* __restrict__ in,
                                                const float* __restrict__ mod,
                                                int sh_off, int sc_off,
                                                float* __restrict__ out) {
    const int row = blockIdx.x;
    const float* xr = in + (size_t)row*D_;
    const int t = threadIdx.x;
    float v0 = xr[t], v1 = xr[t+256];
    float s = v0 + v1, q = v0*v0 + v1*v1;
    __shared__ float ss[8], sq[8];
    int lane = t & 31, w = t >> 5;
    #pragma unroll
    for (int o = 16; o; o >>= 1) {
        s += __shfl_down_sync(0xffffffffu, s, o);
        q += __shfl_down_sync(0xffffffffu, q, o);
    }
    if (!lane) { ss[w] = s; sq[w] = q; }
    __syncthreads();
    if (t == 0) {
        float S = 0.f, Q = 0.f;
        #pragma unroll
        for (int i = 0; i < 8; i++) { S += ss[i]; Q += sq[i]; }
        ss[0] = S; sq[0] = Q;
    }
    __syncthreads();
    float mean = ss[0] * (1.f/512.f);
    float var  = sq[0] * (1.f/512.f) - mean*mean;
    float inv  = rsqrtf(var + 1e-5f);
    const float* mrow = mod + (size_t)row*(6*D_);
    out[(size_t)row*D_ + t]       = (v0-mean)*inv*(1.f + mrow[sc_off + t])     + mrow[sh_off + t];
    out[(size_t)row*D_ + t + 256] = (v1-mean)*inv*(1.f + mrow[sc_off + t+256]) + mrow[sh_off + t+256];
}

// ------------------------- generic SGEMM: C = A @ W^T (+bias) + epilogue -------------------------
#define EPI_PLAIN   0
#define EPI_SILU    1
#define EPI_XCOND   2
#define EPI_GELU    3
#define EPI_GATERES 4

template<int BM, int BN, int TM, int TN, int EPI>
__global__ void __launch_bounds__(256)
gemm_k(const float* __restrict__ A, const float* __restrict__ W,
       const float* __restrict__ bias, float* __restrict__ C,
       int K, int N,
       const float* __restrict__ aux,   // XCOND: x [L,B,D]; GATERES: residual [M,D]
       const float* __restrict__ gate)  // GATERES: g_mod + gate offset (row stride 6D)
{
    static_assert((BM/TM)*(BN/TN) == 256, "256 threads");
    __shared__ __align__(16) float As[16][BM];
    __shared__ __align__(16) float Ws[16][BN];
    const int tid = threadIdx.x;
    const int TX = BN / TN;
    const int tx = tid % TX, ty = tid / TX;
    const int m0 = blockIdx.y * BM, n0 = blockIdx.x * BN;

    float acc[TM][TN];
    #pragma unroll
    for (int i = 0; i < TM; i++)
        #pragma unroll
        for (int j = 0; j < TN; j++) acc[i][j] = 0.f;

    for (int k0 = 0; k0 < K; k0 += 16) {
        #pragma unroll
        for (int i = tid; i < BM*4; i += 256) {
            int r = i >> 2, c4 = (i & 3) * 4;
            float4 v = *(const float4*)(A + (size_t)(m0 + r)*K + k0 + c4);
            As[c4+0][r] = v.x; As[c4+1][r] = v.y; As[c4+2][r] = v.z; As[c4+3][r] = v.w;
        }
        #pragma unroll
        for (int i = tid; i < BN*4; i += 256) {
            int r = i >> 2, c4 = (i & 3) * 4;
            float4 v = *(const float4*)(W + (size_t)(n0 + r)*K + k0 + c4);
            Ws[c4+0][r] = v.x; Ws[c4+1][r] = v.y; Ws[c4+2][r] = v.z; Ws[c4+3][r] = v.w;
        }
        __syncthreads();
        #pragma unroll
        for (int k = 0; k < 16; k++) {
            float a[TM], b[TN];
            #pragma unroll
            for (int i = 0; i < TM; i += 4) {
                float4 v = *(const float4*)&As[k][ty*TM + i];
                a[i] = v.x; a[i+1] = v.y; a[i+2] = v.z; a[i+3] = v.w;
            }
            #pragma unroll
            for (int j = 0; j < TN; j += 4) {
                float4 v = *(const float4*)&Ws[k][tx*TN + j];
                b[j] = v.x; b[j+1] = v.y; b[j+2] = v.z; b[j+3] = v.w;
            }
            #pragma unroll
            for (int i = 0; i < TM; i++)
                #pragma unroll
                for (int j = 0; j < TN; j++)
                    acc[i][j] = fmaf(a[i], b[j], acc[i][j]);
        }
        __syncthreads();
    }

    #pragma unroll
    for (int i = 0; i < TM; i++) {
        int gm = m0 + ty*TM + i;
        #pragma unroll
        for (int j = 0; j < TN; j++) {
            int gn = n0 + tx*TN + j;
            float v = acc[i][j];
            if (bias) v += bias[gn];
            float outv;
            if (EPI == EPI_PLAIN) {
                outv = v;
            } else if (EPI == EPI_SILU) {
                outv = siluf(v);
            } else if (EPI == EPI_XCOND) {
                int bb = gm >> 9, ll = gm & 511;
                outv = siluf(aux[((size_t)(ll*B_ + bb))*D_ + gn] + v);
            } else if (EPI == EPI_GELU) {
                outv = geluf(v);
            } else {  // EPI_GATERES (N == D_)
                outv = aux[(size_t)gm*D_ + gn] + gate[(size_t)gm*(6*D_) + gn] * v;
            }
            C[(size_t)gm*N + gn] = outv;
        }
    }
}

// ------------------------- attention scores -------------------------
__global__ void __launch_bounds__(256) attn_scores_k() {
    __shared__ float Qs[64][33];
    __shared__ float Ks[64][33];
    const int bh = blockIdx.z, b = bh >> 4, h = bh & 15;
    const int l0 = blockIdx.y * 64, m0 = blockIdx.x * 64;
    const int tid = threadIdx.x;
    const float* qbase = g_qkv + ((size_t)(b*L_ + l0)) * 1536 + h * 32;
    const float* kbase = g_qkv + ((size_t)(b*L_ + m0)) * 1536 + 512 + h * 32;
    #pragma unroll
    for (int i = tid; i < 512; i += 256) {
        int r = i >> 3, c4 = (i & 7) * 4;
        float4 q4 = *(const float4*)(qbase + (size_t)r * 1536 + c4);
        Qs[r][c4] = q4.x; Qs[r][c4+1] = q4.y; Qs[r][c4+2] = q4.z; Qs[r][c4+3] = q4.w;
        float4 k4 = *(const float4*)(kbase + (size_t)r * 1536 + c4);
        Ks[r][c4] = k4.x; Ks[r][c4+1] = k4.y; Ks[r][c4+2] = k4.z; Ks[r][c4+3] = k4.w;
    }
    __syncthreads();
    const int tx = tid & 15, ty = tid >> 4;
    float acc[4][4] = {};
    #pragma unroll
    for (int k = 0; k < 32; k++) {
        float a[4], bb[4];
        #pragma unroll
        for (int i = 0; i < 4; i++) a[i] = Qs[ty*4 + i][k];
        #pragma unroll
        for (int j = 0; j < 4; j++) bb[j] = Ks[tx*4 + j][k];
        #pragma unroll
        for (int i = 0; i < 4; i++)
            #pragma unroll
            for (int j = 0; j < 4; j++)
                acc[i][j] = fmaf(a[i], bb[j], acc[i][j]);
    }
    const float scale = 0.17677669529663687f;  // 1/sqrt(32)
    #pragma unroll
    for (int i = 0; i < 4; i++) {
        int l = l0 + ty*4 + i;
        size_t srow = ((size_t)(bh*L_ + l)) * L_;
        #pragma unroll
        for (int j = 0; j < 4; j++) {
            int m = m0 + tx*4 + j;
            float v = acc[i][j] * scale + g_pfb[srow + m];
            if (g_keep[b*L_ + m] == 0.f) v = -1e9f;
            g_s[srow + m] = v;
        }
    }
}

// ------------------------- softmax over last dim of g_s -------------------------
__global__ void __launch_bounds__(256) softmax_k() {
    const size_t base = (size_t)blockIdx.x * 512;
    const int t = threadIdx.x;
    float v0 = g_s[base + t], v1 = g_s[base + t + 256];
    __shared__ float red[8];
    __shared__ float red2[8];
    int lane = t & 31, w = t >> 5;
    float m = fmaxf(v0, v1);
    #pragma unroll
    for (int o = 16; o; o >>= 1) m = fmaxf(m, __shfl_down_sync(0xffffffffu, m, o));
    if (!lane) red[w] = m;
    __syncthreads();
    if (t == 0) {
        float M = red[0];
        #pragma unroll
        for (int i = 1; i < 8; i++) M = fmaxf(M, red[i]);
        red[0] = M;
    }
    __syncthreads();
    float M = red[0];
    float e0 = __expf(v0 - M), e1 = __expf(v1 - M);
    float s = e0 + e1;
    #pragma unroll
    for (int o = 16; o; o >>= 1) s += __shfl_down_sync(0xffffffffu, s, o);
    if (!lane) red2[w] = s;
    __syncthreads();
    if (t == 0) {
        float S = 0.f;
        #pragma unroll
        for (int i = 0; i < 8; i++) S += red2[i];
        red2[0] = 1.f / S;
    }
    __syncthreads();
    float inv = red2[0];
    g_s[base + t] = e0 * inv;
    g_s[base + t + 256] = e1 * inv;
}

// ------------------------- O = P @ V -------------------------
__global__ void __launch_bounds__(256) attn_o_k() {
    __shared__ float Ps[64][65];
    __shared__ float Vs[64][33];
    const int bh = blockIdx.y, b = bh >> 4, h = bh & 15;
    const int l0 = blockIdx.x * 64;
    const int tid = threadIdx.x;
    const int tx = tid & 31, ty = tid >> 5;
    float acc[8] = {};
    for (int m0 = 0; m0 < 512; m0 += 64) {
        #pragma unroll
        for (int i = tid; i < 1024; i += 256) {
            int r = i >> 4, c4 = (i & 15) * 4;
            float4 p4 = *(const float4*)(g_s + ((size_t)(bh*L_ + l0 + r))*L_ + m0 + c4);
            Ps[r][c4] = p4.x; Ps[r][c4+1] = p4.y; Ps[r][c4+2] = p4.z; Ps[r][c4+3] = p4.w;
        }
        #pragma unroll
        for (int i = tid; i < 512; i += 256) {
            int r = i >> 3, c4 = (i & 7) * 4;
            float4 v4 = *(const float4*)(g_qkv + ((size_t)(b*L_ + m0 + r))*1536 + 1024 + h*32 + c4);
            Vs[r][c4] = v4.x; Vs[r][c4+1] = v4.y; Vs[r][c4+2] = v4.z; Vs[r][c4+3] = v4.w;
        }
        __syncthreads();
        #pragma unroll 16
        for (int m = 0; m < 64; m++) {
            float v = Vs[m][tx];
            #pragma unroll
            for (int i = 0; i < 8; i++)
                acc[i] = fmaf(Ps[ty + 8*i][m], v, acc[i]);
        }
        __syncthreads();
    }
    #pragma unroll
    for (int i = 0; i < 8; i++) {
        int l = l0 + ty + 8*i;
        g_o[((size_t)(b*L_ + l))*D_ + h*32 + tx] = acc[i];
    }
}

// ------------------------- host launch -------------------------
extern "C" void kernel_launch(void* const* d_in, const int* in_sizes, int n_in,
                              void* d_out, int out_size) {
    const float* x        = (const float*)d_in[0];
    const float* pos      = (const float*)d_in[1];
    const float* time_emb = (const float*)d_in[2];
    const float* pair     = (const float*)d_in[3];
    const float* pos_w    = (const float*)d_in[4];
    const float* pfb_w    = (const float*)d_in[5];
    const float* p2n_w1   = (const float*)d_in[6];
    const float* p2n_w2   = (const float*)d_in[7];
    const float* adaln_w  = (const float*)d_in[8];
    const float* adaln_b  = (const float*)d_in[9];
    const float* qkv_w    = (const float*)d_in[10];
    const float* qkv_b    = (const float*)d_in[11];
    const float* proj_w   = (const float*)d_in[12];
    const float* proj_b   = (const float*)d_in[13];
    const float* mlp_w1   = (const float*)d_in[14];
    const float* mlp_b1   = (const float*)d_in[15];
    const float* mlp_w2   = (const float*)d_in[16];
    const float* mlp_b2   = (const float*)d_in[17];
    const unsigned int* mask = (const unsigned int*)d_in[18];

    float *p_f2n, *p_cond, *p_h, *p_hin, *p_mod, *p_a, *p_qkv, *p_o, *p_hin2, *p_m2, *p_t;
    cudaGetSymbolAddress((void**)&p_f2n,  g_f2n);
    cudaGetSymbolAddress((void**)&p_cond, g_cond);
    cudaGetSymbolAddress((void**)&p_h,    g_h);
    cudaGetSymbolAddress((void**)&p_hin,  g_hin);
    cudaGetSymbolAddress((void**)&p_mod,  g_mod);
    cudaGetSymbolAddress((void**)&p_a,    g_a);
    cudaGetSymbolAddress((void**)&p_qkv,  g_qkv);
    cudaGetSymbolAddress((void**)&p_o,    g_o);
    cudaGetSymbolAddress((void**)&p_hin2, g_hin2);
    cudaGetSymbolAddress((void**)&p_m2,   g_m2);
    cudaGetSymbolAddress((void**)&p_t,    g_t);

    decode_mask_k<<<1, 1024>>>(mask);
    pos_emb_k<<<(M_*D_)/256, 256>>>(pos, pos_w);
    pfb_k<<<dim3(L_/32, L_, B_), 256>>>(pair, pfb_w);
    topk_k<<<M_/8, 256>>>();
    f2n_k<<<M_, 128>>>(pair);

    // pair2node MLP: silu(f2n @ w1^T) @ w2^T ; cond = silu(x + result)
    gemm_k<64,64,4,4,EPI_SILU><<<dim3(P_/64, M_/64), 256>>>(
        p_f2n, p2n_w1, nullptr, p_t, P_, P_, nullptr, nullptr);
    gemm_k<64,64,4,4,EPI_XCOND><<<dim3(D_/64, M_/64), 256>>>(
        p_t, p2n_w2, nullptr, p_cond, P_, D_, x, nullptr);

    for (int l = 0; l < NL_; l++) {
        add_te_k<<<(M_*D_)/256, 256>>>(time_emb);
        // mod = cond @ adaln_w^T + adaln_b  [1024, 3072]
        gemm_k<128,128,8,8,EPI_PLAIN><<<dim3(6*D_/128, M_/128), 256>>>(
            p_cond, adaln_w + (size_t)l*6*D_*D_, adaln_b + (size_t)l*6*D_,
            p_mod, D_, 6*D_, nullptr, nullptr);
        // a = ln(hin)*(1+sc_a)+sh_a
        ln_mod_k<<<M_, 256>>>(p_hin, p_mod, 0, D_, p_a);
        // qkv = a @ qkv_w^T + qkv_b  [1024, 1536]
        gemm_k<128,128,8,8,EPI_PLAIN><<<dim3(3*D_/128, M_/128), 256>>>(
            p_a, qkv_w + (size_t)l*3*D_*D_, qkv_b + (size_t)l*3*D_,
            p_qkv, D_, 3*D_, nullptr, nullptr);
        // attention
        attn_scores_k<<<dim3(L_/64, L_/64, B_*H_), 256>>>();
        softmax_k<<<B_*H_*L_, 256>>>();
        attn_o_k<<<dim3(L_/64, B_*H_), 256>>>();
        // hin2 = hin + g_a * (o @ proj_w^T + proj_b)
        gemm_k<64,64,4,4,EPI_GATERES><<<dim3(D_/64, M_/64), 256>>>(
            p_o, proj_w + (size_t)l*D_*D_, proj_b + (size_t)l*D_,
            p_hin2, D_, D_, p_hin, p_mod + 2*D_);
        // m = ln(hin2)*(1+sc_m)+sh_m
        ln_mod_k<<<M_, 256>>>(p_hin2, p_mod, 3*D_, 4*D_, p_m2);
        // t = gelu(m @ mlp_w1^T + b1)  [1024, 2048]
        gemm_k<128,128,8,8,EPI_GELU><<<dim3(FF_/128, M_/128), 256>>>(
            p_m2, mlp_w1 + (size_t)l*FF_*D_, mlp_b1 + (size_t)l*FF_,
            p_t, D_, FF_, nullptr, nullptr);
        // h = hin2 + g_m * (t @ mlp_w2^T + b2)  -> d_out on last layer
        float* dst = (l == NL_-1) ? (float*)d_out : p_h;
        gemm_k<64,64,4,4,EPI_GATERES><<<dim3(D_/64, M_/64), 256>>>(
            p_t, mlp_w2 + (size_t)l*D_*FF_, mlp_b2 + (size_t)l*D_,
            dst, FF_, D_, p_hin2, p_mod + 5*D_);
    }
    (void)in_sizes; (void)n_in; (void)out_size;
}

// round 9
// speedup vs baseline: 1.1902x; 1.1895x over previous
#include <cuda_runtime.h>
#include <cuda_bf16.h>
#include <cstdint>
#include <cstddef>

#define B_ 2
#define L_ 512
#define D_ 512
#define H_ 16
#define P_ 128
#define NL_ 2
#define FF_ 2048
#define M_ (B_*L_)

// ------------------------- static device scratch -------------------------
__device__ float g_keep[M_];
__device__ float g_pfb[(size_t)B_*H_*L_*L_];
__device__ float g_hsum[(size_t)B_*L_*L_];
__device__ int   g_topk[M_*3];
__device__ float g_f2n[M_*P_];
__device__ float g_cond[M_*D_];
__device__ float g_h[M_*D_];
__device__ float g_hin[M_*D_];
__device__ float g_mod[(size_t)M_*6*D_];
__device__ float g_a[M_*D_];
__device__ float g_qkv[M_*3*D_];
__device__ float g_s[(size_t)B_*H_*L_*L_];
__device__ float g_o[M_*D_];
__device__ float g_hin2[M_*D_];
__device__ float g_m2[M_*D_];
__device__ float g_t[(size_t)M_*FF_];

__device__ __forceinline__ float siluf(float x){ return x * (1.f/(1.f + __expf(-x))); }
__device__ __forceinline__ float geluf(float x){
    return 0.5f*x*(1.f + tanhf(0.79788456080286536f*(x + 0.044715f*x*x*x)));
}

// ------------------------- mma.sync bf16 GEMM: C = A @ W^T (+bias) + epilogue -------------
#define EPI_PLAIN   0
#define EPI_SILU    1
#define EPI_XCOND   2
#define EPI_GELU    3
#define EPI_GATERES 4

#define MMA4(c, a, b0, b1) \
    asm volatile("mma.sync.aligned.m16n8k16.row.col.f32.bf16.bf16.f32 " \
        "{%0,%1,%2,%3}, {%4,%5,%6,%7}, {%8,%9}, {%0,%1,%2,%3};" \
        : "+f"((c)[0]), "+f"((c)[1]), "+f"((c)[2]), "+f"((c)[3]) \
        : "r"((a)[0]), "r"((a)[1]), "r"((a)[2]), "r"((a)[3]), "r"(b0), "r"(b1))

template<int EPI>
__global__ void __launch_bounds__(256)
gemm_k(const float* __restrict__ A, const float* __restrict__ W,
       const float* __restrict__ bias, float* __restrict__ C,
       int K, int N,
       const float* __restrict__ aux,   // XCOND: x [L,B,D]; GATERES: residual [M,D]
       const float* __restrict__ gate)  // GATERES: g_mod + gate offset (row stride 6D)
{
    __shared__ __align__(16) __nv_bfloat16 sAh[128][40];
    __shared__ __align__(16) __nv_bfloat16 sAl[128][40];
    __shared__ __align__(16) __nv_bfloat16 sWh[128][40];
    __shared__ __align__(16) __nv_bfloat16 sWl[128][40];

    const int tid = threadIdx.x;
    const int wid = tid >> 5, lane = tid & 31;
    const int g = lane >> 2, tq = lane & 3;
    const int m0 = blockIdx.y << 7, n0 = blockIdx.x << 7;
    const int wm0 = (wid & 1) << 6;        // warp row offset (0/64)
    const int wn0 = (wid >> 1) << 5;       // warp col offset (0/32/64/96)

    float c[4][4][4];
    #pragma unroll
    for (int i = 0; i < 4; i++)
        #pragma unroll
        for (int j = 0; j < 4; j++)
            #pragma unroll
            for (int r = 0; r < 4; r++) c[i][j][r] = 0.f;

    for (int k0 = 0; k0 < K; k0 += 32) {
        // ---- global fp32 -> smem bf16 hi/lo (both tiles) ----
        #pragma unroll
        for (int t2 = 0; t2 < 2; t2++) {
            const float* G = t2 ? W : A;
            const int r0 = t2 ? n0 : m0;
            __nv_bfloat16 (*sh)[40] = t2 ? sWh : sAh;
            __nv_bfloat16 (*sl)[40] = t2 ? sWl : sAl;
            #pragma unroll
            for (int i = 0; i < 4; i++) {
                int u = (i << 8) + tid;            // 0..1023
                int row = u >> 3, q = (u & 7) << 2;
                float4 v = *(const float4*)(G + (size_t)(r0 + row)*K + k0 + q);
                float f[4] = {v.x, v.y, v.z, v.w};
                __nv_bfloat16 h[4], l[4];
                #pragma unroll
                for (int d = 0; d < 4; d++) {
                    h[d] = __float2bfloat16(f[d]);
                    l[d] = __float2bfloat16(f[d] - __bfloat162float(h[d]));
                }
                __nv_bfloat162 h01 = __halves2bfloat162(h[0], h[1]);
                __nv_bfloat162 h23 = __halves2bfloat162(h[2], h[3]);
                __nv_bfloat162 l01 = __halves2bfloat162(l[0], l[1]);
                __nv_bfloat162 l23 = __halves2bfloat162(l[2], l[3]);
                uint2 hp, lp;
                hp.x = *(uint32_t*)&h01; hp.y = *(uint32_t*)&h23;
                lp.x = *(uint32_t*)&l01; lp.y = *(uint32_t*)&l23;
                *(uint2*)&sh[row][q] = hp;
                *(uint2*)&sl[row][q] = lp;
            }
        }
        __syncthreads();

        // ---- two k-steps of 16 ----
        #pragma unroll
        for (int ks = 0; ks < 32; ks += 16) {
            uint32_t aH[4][4], aL[4][4];
            #pragma unroll
            for (int mt = 0; mt < 4; mt++) {
                int r = wm0 + (mt << 4) + g;
                int kc = ks + 2*tq;
                aH[mt][0] = *(uint32_t*)&sAh[r  ][kc];
                aH[mt][1] = *(uint32_t*)&sAh[r+8][kc];
                aH[mt][2] = *(uint32_t*)&sAh[r  ][kc+8];
                aH[mt][3] = *(uint32_t*)&sAh[r+8][kc+8];
                aL[mt][0] = *(uint32_t*)&sAl[r  ][kc];
                aL[mt][1] = *(uint32_t*)&sAl[r+8][kc];
                aL[mt][2] = *(uint32_t*)&sAl[r  ][kc+8];
                aL[mt][3] = *(uint32_t*)&sAl[r+8][kc+8];
            }
            #pragma unroll
            for (int nt = 0; nt < 4; nt++) {
                int rn = wn0 + (nt << 3) + g;
                int kc = ks + 2*tq;
                uint32_t bH0 = *(uint32_t*)&sWh[rn][kc];
                uint32_t bH1 = *(uint32_t*)&sWh[rn][kc+8];
                uint32_t bL0 = *(uint32_t*)&sWl[rn][kc];
                uint32_t bL1 = *(uint32_t*)&sWl[rn][kc+8];
                #pragma unroll
                for (int mt = 0; mt < 4; mt++) {
                    MMA4(c[mt][nt], aH[mt], bH0, bH1);
                    MMA4(c[mt][nt], aH[mt], bL0, bL1);
                    MMA4(c[mt][nt], aL[mt], bH0, bH1);
                }
            }
        }
        __syncthreads();
    }

    // ---- epilogue ----
    #pragma unroll
    for (int mt = 0; mt < 4; mt++) {
        #pragma unroll
        for (int nt = 0; nt < 4; nt++) {
            int gn = n0 + wn0 + (nt << 3) + 2*tq;
            #pragma unroll
            for (int hf = 0; hf < 2; hf++) {
                int gm = m0 + wm0 + (mt << 4) + g + (hf << 3);
                float v0 = c[mt][nt][hf*2+0];
                float v1 = c[mt][nt][hf*2+1];
                if (bias) { v0 += bias[gn]; v1 += bias[gn+1]; }
                if (EPI == EPI_SILU) {
                    v0 = siluf(v0); v1 = siluf(v1);
                } else if (EPI == EPI_XCOND) {
                    int bb = gm >> 9, ll = gm & 511;
                    const float* xr = aux + ((size_t)(ll*B_ + bb))*D_ + gn;
                    v0 = siluf(xr[0] + v0); v1 = siluf(xr[1] + v1);
                } else if (EPI == EPI_GELU) {
                    v0 = geluf(v0); v1 = geluf(v1);
                } else if (EPI == EPI_GATERES) {
                    const float* ar = aux + (size_t)gm*D_ + gn;
                    const float* gr = gate + (size_t)gm*(6*D_) + gn;
                    v0 = ar[0] + gr[0]*v0; v1 = ar[1] + gr[1]*v1;
                }
                *(float2*)(C + (size_t)gm*N + gn) = make_float2(v0, v1);
            }
        }
    }
}

// ------------------------- mask decode -------------------------
__global__ void decode_mask_k(const unsigned int* __restrict__ raw) {
    int t = threadIdx.x;
    g_keep[t] = (raw[t] == 0u) ? 1.f : 0.f;
}

// ------------------------- pos embedding -------------------------
__global__ void __launch_bounds__(256) pos_emb_k(const float* __restrict__ pos,
                                                 const float* __restrict__ pw) {
    int i = blockIdx.x*256 + threadIdx.x;
    int row = i >> 9, d = i & 511;
    float v = pos[row*3+0]*pw[d*3+0] + pos[row*3+1]*pw[d*3+1] + pos[row*3+2]*pw[d*3+2];
    g_h[i] = g_keep[row] * v;
}

// ------------------------- pair bias + head-sum -------------------------
__global__ void __launch_bounds__(256) pfb_k(const float* __restrict__ pair,
                                             const float* __restrict__ pfbw) {
    __shared__ float sp[32][129];
    __shared__ float sw[16][128];
    __shared__ float shs[32];
    const int b = blockIdx.z, l = blockIdx.y, m0 = blockIdx.x * 32;
    const int tid = threadIdx.x;
    for (int i = tid; i < 512; i += 256) {
        float4 v = ((const float4*)pfbw)[i];
        int hh = i >> 5, p = (i & 31) * 4;
        sw[hh][p] = v.x; sw[hh][p+1] = v.y; sw[hh][p+2] = v.z; sw[hh][p+3] = v.w;
    }
    if (tid < 32) shs[tid] = 0.f;
    const float* src = pair + (((size_t)(b * L_ + l)) * L_ + m0) * P_;
    for (int i = tid; i < 1024; i += 256) {
        float4 v = ((const float4*)src)[i];
        int mm = i >> 5, p = (i & 31) * 4;
        sp[mm][p]   = siluf(v.x); sp[mm][p+1] = siluf(v.y);
        sp[mm][p+2] = siluf(v.z); sp[mm][p+3] = siluf(v.w);
    }
    __syncthreads();
    const int m = tid & 31, h0 = (tid >> 5) * 2;
    float a0 = 0.f, a1 = 0.f;
    #pragma unroll 16
    for (int p = 0; p < 128; p++) {
        float v = sp[m][p];
        a0 = fmaf(v, sw[h0][p], a0);
        a1 = fmaf(v, sw[h0+1][p], a1);
    }
    size_t base = ((size_t)((b*H_ + h0) * L_ + l)) * L_ + m0 + m;
    g_pfb[base] = a0;
    g_pfb[base + (size_t)L_*L_] = a1;
    atomicAdd(&shs[m], a0 + a1);
    __syncthreads();
    if (tid < 32)
        g_hsum[((size_t)(b*L_ + l))*L_ + m0 + tid] = shs[tid];
}

// ------------------------- top-3 rows per (b, column m) -------------------------
__global__ void __launch_bounds__(256) topk_k() {
    const int warp = threadIdx.x >> 5, lane = threadIdx.x & 31;
    const int bm = blockIdx.x * 8 + warp;
    const int b = bm >> 9, m = bm & 511;
    float lv[3] = {-3.4e38f, -3.4e38f, -3.4e38f};
    int   li[3] = {0x7fffffff, 0x7fffffff, 0x7fffffff};
    for (int l = lane; l < L_; l += 32) {
        float s = g_hsum[((size_t)(b*L_ + l))*L_ + m];
        if (s > lv[0])      { lv[2]=lv[1]; li[2]=li[1]; lv[1]=lv[0]; li[1]=li[0]; lv[0]=s; li[0]=l; }
        else if (s > lv[1]) { lv[2]=lv[1]; li[2]=li[1]; lv[1]=s; li[1]=l; }
        else if (s > lv[2]) { lv[2]=s; li[2]=l; }
    }
    int ptr = 0;
    for (int r = 0; r < 3; r++) {
        float bv = (ptr < 3) ? lv[ptr] : -3.4e38f;
        int   bi = (ptr < 3) ? li[ptr] : 0x7fffffff;
        int   bl = lane;
        #pragma unroll
        for (int o = 16; o; o >>= 1) {
            float ov = __shfl_down_sync(0xffffffffu, bv, o);
            int   oi = __shfl_down_sync(0xffffffffu, bi, o);
            int   ol = __shfl_down_sync(0xffffffffu, bl, o);
            if (ov > bv || (ov == bv && oi < bi)) { bv = ov; bi = oi; bl = ol; }
        }
        bi = __shfl_sync(0xffffffffu, bi, 0);
        bl = __shfl_sync(0xffffffffu, bl, 0);
        if (lane == bl) ptr++;
        if (lane == 0) g_topk[bm*3 + r] = bi;
    }
}

// ------------------------- f2n gather -------------------------
__global__ void __launch_bounds__(128) f2n_k(const float* __restrict__ pair) {
    const int bm = blockIdx.x;
    const int b = bm >> 9, m = bm & 511;
    const int p = threadIdx.x;
    float acc = 0.f;
    #pragma unroll
    for (int t = 0; t < 3; t++) {
        int l = g_topk[bm*3 + t];
        acc += g_keep[b*L_ + l] * pair[(((size_t)(b*L_ + l))*L_ + m)*P_ + p];
    }
    g_f2n[bm*P_ + p] = acc * g_keep[bm] * (1.f/3.f);
}

// ------------------------- hin = h + time_emb -------------------------
__global__ void __launch_bounds__(256) add_te_k(const float* __restrict__ te) {
    int i = blockIdx.x*256 + threadIdx.x;
    int row = i >> 9;
    int b = row >> 9;
    g_hin[i] = g_h[i] + te[(b << 9) + (i & 511)];
}

// ------------------------- LayerNorm + adaLN modulation -------------------------
__global__ void __launch_bounds__(256) ln_mod_k(const float* __restrict__ in,
                                                const float* __restrict__ mod,
                                                int sh_off, int sc_off,
                                                float* __restrict__ out) {
    const int row = blockIdx.x;
    const float* xr = in + (size_t)row*D_;
    const int t = threadIdx.x;
    float v0 = xr[t], v1 = xr[t+256];
    float s = v0 + v1, q = v0*v0 + v1*v1;
    __shared__ float ss[8], sq[8];
    int lane = t & 31, w = t >> 5;
    #pragma unroll
    for (int o = 16; o; o >>= 1) {
        s += __shfl_down_sync(0xffffffffu, s, o);
        q += __shfl_down_sync(0xffffffffu, q, o);
    }
    if (!lane) { ss[w] = s; sq[w] = q; }
    __syncthreads();
    if (t == 0) {
        float S = 0.f, Q = 0.f;
        #pragma unroll
        for (int i = 0; i < 8; i++) { S += ss[i]; Q += sq[i]; }
        ss[0] = S; sq[0] = Q;
    }
    __syncthreads();
    float mean = ss[0] * (1.f/512.f);
    float var  = sq[0] * (1.f/512.f) - mean*mean;
    float inv  = rsqrtf(var + 1e-5f);
    const float* mrow = mod + (size_t)row*(6*D_);
    out[(size_t)row*D_ + t]       = (v0-mean)*inv*(1.f + mrow[sc_off + t])     + mrow[sh_off + t];
    out[(size_t)row*D_ + t + 256] = (v1-mean)*inv*(1.f + mrow[sc_off + t+256]) + mrow[sh_off + t+256];
}

// ------------------------- attention scores -------------------------
__global__ void __launch_bounds__(256) attn_scores_k() {
    __shared__ float Qs[64][33];
    __shared__ float Ks[64][33];
    const int bh = blockIdx.z, b = bh >> 4, h = bh & 15;
    const int l0 = blockIdx.y * 64, m0 = blockIdx.x * 64;
    const int tid = threadIdx.x;
    const float* qbase = g_qkv + ((size_t)(b*L_ + l0)) * 1536 + h * 32;
    const float* kbase = g_qkv + ((size_t)(b*L_ + m0)) * 1536 + 512 + h * 32;
    #pragma unroll
    for (int i = tid; i < 512; i += 256) {
        int r = i >> 3, c4 = (i & 7) * 4;
        float4 q4 = *(const float4*)(qbase + (size_t)r * 1536 + c4);
        Qs[r][c4] = q4.x; Qs[r][c4+1] = q4.y; Qs[r][c4+2] = q4.z; Qs[r][c4+3] = q4.w;
        float4 k4 = *(const float4*)(kbase + (size_t)r * 1536 + c4);
        Ks[r][c4] = k4.x; Ks[r][c4+1] = k4.y; Ks[r][c4+2] = k4.z; Ks[r][c4+3] = k4.w;
    }
    __syncthreads();
    const int tx = tid & 15, ty = tid >> 4;
    float acc[4][4] = {};
    #pragma unroll
    for (int k = 0; k < 32; k++) {
        float a[4], bb[4];
        #pragma unroll
        for (int i = 0; i < 4; i++) a[i] = Qs[ty*4 + i][k];
        #pragma unroll
        for (int j = 0; j < 4; j++) bb[j] = Ks[tx*4 + j][k];
        #pragma unroll
        for (int i = 0; i < 4; i++)
            #pragma unroll
            for (int j = 0; j < 4; j++)
                acc[i][j] = fmaf(a[i], bb[j], acc[i][j]);
    }
    const float scale = 0.17677669529663687f;
    #pragma unroll
    for (int i = 0; i < 4; i++) {
        int l = l0 + ty*4 + i;
        size_t srow = ((size_t)(bh*L_ + l)) * L_;
        #pragma unroll
        for (int j = 0; j < 4; j++) {
            int m = m0 + tx*4 + j;
            float v = acc[i][j] * scale + g_pfb[srow + m];
            if (g_keep[b*L_ + m] == 0.f) v = -1e9f;
            g_s[srow + m] = v;
        }
    }
}

// ------------------------- softmax -------------------------
__global__ void __launch_bounds__(256) softmax_k() {
    const size_t base = (size_t)blockIdx.x * 512;
    const int t = threadIdx.x;
    float v0 = g_s[base + t], v1 = g_s[base + t + 256];
    __shared__ float red[8];
    __shared__ float red2[8];
    int lane = t & 31, w = t >> 5;
    float m = fmaxf(v0, v1);
    #pragma unroll
    for (int o = 16; o; o >>= 1) m = fmaxf(m, __shfl_down_sync(0xffffffffu, m, o));
    if (!lane) red[w] = m;
    __syncthreads();
    if (t == 0) {
        float M = red[0];
        #pragma unroll
        for (int i = 1; i < 8; i++) M = fmaxf(M, red[i]);
        red[0] = M;
    }
    __syncthreads();
    float M = red[0];
    float e0 = __expf(v0 - M), e1 = __expf(v1 - M);
    float s = e0 + e1;
    #pragma unroll
    for (int o = 16; o; o >>= 1) s += __shfl_down_sync(0xffffffffu, s, o);
    if (!lane) red2[w] = s;
    __syncthreads();
    if (t == 0) {
        float S = 0.f;
        #pragma unroll
        for (int i = 0; i < 8; i++) S += red2[i];
        red2[0] = 1.f / S;
    }
    __syncthreads();
    float inv = red2[0];
    g_s[base + t] = e0 * inv;
    g_s[base + t + 256] = e1 * inv;
}

// ------------------------- O = P @ V -------------------------
__global__ void __launch_bounds__(256) attn_o_k() {
    __shared__ float Ps[64][65];
    __shared__ float Vs[64][33];
    const int bh = blockIdx.y, b = bh >> 4, h = bh & 15;
    const int l0 = blockIdx.x * 64;
    const int tid = threadIdx.x;
    const int tx = tid & 31, ty = tid >> 5;
    float acc[8] = {};
    for (int m0 = 0; m0 < 512; m0 += 64) {
        #pragma unroll
        for (int i = tid; i < 1024; i += 256) {
            int r = i >> 4, c4 = (i & 15) * 4;
            float4 p4 = *(const float4*)(g_s + ((size_t)(bh*L_ + l0 + r))*L_ + m0 + c4);
            Ps[r][c4] = p4.x; Ps[r][c4+1] = p4.y; Ps[r][c4+2] = p4.z; Ps[r][c4+3] = p4.w;
        }
        #pragma unroll
        for (int i = tid; i < 512; i += 256) {
            int r = i >> 3, c4 = (i & 7) * 4;
            float4 v4 = *(const float4*)(g_qkv + ((size_t)(b*L_ + m0 + r))*1536 + 1024 + h*32 + c4);
            Vs[r][c4] = v4.x; Vs[r][c4+1] = v4.y; Vs[r][c4+2] = v4.z; Vs[r][c4+3] = v4.w;
        }
        __syncthreads();
        #pragma unroll 16
        for (int m = 0; m < 64; m++) {
            float v = Vs[m][tx];
            #pragma unroll
            for (int i = 0; i < 8; i++)
                acc[i] = fmaf(Ps[ty + 8*i][m], v, acc[i]);
        }
        __syncthreads();
    }
    #pragma unroll
    for (int i = 0; i < 8; i++) {
        int l = l0 + ty + 8*i;
        g_o[((size_t)(b*L_ + l))*D_ + h*32 + tx] = acc[i];
    }
}

// ------------------------- host launch -------------------------
extern "C" void kernel_launch(void* const* d_in, const int* in_sizes, int n_in,
                              void* d_out, int out_size) {
    const float* x        = (const float*)d_in[0];
    const float* pos      = (const float*)d_in[1];
    const float* time_emb = (const float*)d_in[2];
    const float* pair     = (const float*)d_in[3];
    const float* pos_w    = (const float*)d_in[4];
    const float* pfb_w    = (const float*)d_in[5];
    const float* p2n_w1   = (const float*)d_in[6];
    const float* p2n_w2   = (const float*)d_in[7];
    const float* adaln_w  = (const float*)d_in[8];
    const float* adaln_b  = (const float*)d_in[9];
    const float* qkv_w    = (const float*)d_in[10];
    const float* qkv_b    = (const float*)d_in[11];
    const float* proj_w   = (const float*)d_in[12];
    const float* proj_b   = (const float*)d_in[13];
    const float* mlp_w1   = (const float*)d_in[14];
    const float* mlp_b1   = (const float*)d_in[15];
    const float* mlp_w2   = (const float*)d_in[16];
    const float* mlp_b2   = (const float*)d_in[17];
    const unsigned int* mask = (const unsigned int*)d_in[18];

    float *p_f2n, *p_cond, *p_h, *p_hin, *p_mod, *p_a, *p_qkv, *p_o, *p_hin2, *p_m2, *p_t;
    cudaGetSymbolAddress((void**)&p_f2n,  g_f2n);
    cudaGetSymbolAddress((void**)&p_cond, g_cond);
    cudaGetSymbolAddress((void**)&p_h,    g_h);
    cudaGetSymbolAddress((void**)&p_hin,  g_hin);
    cudaGetSymbolAddress((void**)&p_mod,  g_mod);
    cudaGetSymbolAddress((void**)&p_a,    g_a);
    cudaGetSymbolAddress((void**)&p_qkv,  g_qkv);
    cudaGetSymbolAddress((void**)&p_o,    g_o);
    cudaGetSymbolAddress((void**)&p_hin2, g_hin2);
    cudaGetSymbolAddress((void**)&p_m2,   g_m2);
    cudaGetSymbolAddress((void**)&p_t,    g_t);

    decode_mask_k<<<1, 1024>>>(mask);
    pos_emb_k<<<(M_*D_)/256, 256>>>(pos, pos_w);
    pfb_k<<<dim3(L_/32, L_, B_), 256>>>(pair, pfb_w);
    topk_k<<<M_/8, 256>>>();
    f2n_k<<<M_, 128>>>(pair);

    // pair2node MLP: silu(f2n @ w1^T) @ w2^T ; cond = silu(x + result)
    gemm_k<EPI_SILU><<<dim3(1, 8), 256>>>(
        p_f2n, p2n_w1, nullptr, p_t, P_, P_, nullptr, nullptr);
    gemm_k<EPI_XCOND><<<dim3(4, 8), 256>>>(
        p_t, p2n_w2, nullptr, p_cond, P_, D_, x, nullptr);

    for (int l = 0; l < NL_; l++) {
        add_te_k<<<(M_*D_)/256, 256>>>(time_emb);
        gemm_k<EPI_PLAIN><<<dim3(24, 8), 256>>>(
            p_cond, adaln_w + (size_t)l*6*D_*D_, adaln_b + (size_t)l*6*D_,
            p_mod, D_, 6*D_, nullptr, nullptr);
        ln_mod_k<<<M_, 256>>>(p_hin, p_mod, 0, D_, p_a);
        gemm_k<EPI_PLAIN><<<dim3(12, 8), 256>>>(
            p_a, qkv_w + (size_t)l*3*D_*D_, qkv_b + (size_t)l*3*D_,
            p_qkv, D_, 3*D_, nullptr, nullptr);
        attn_scores_k<<<dim3(L_/64, L_/64, B_*H_), 256>>>();
        softmax_k<<<B_*H_*L_, 256>>>();
        attn_o_k<<<dim3(L_/64, B_*H_), 256>>>();
        gemm_k<EPI_GATERES><<<dim3(4, 8), 256>>>(
            p_o, proj_w + (size_t)l*D_*D_, proj_b + (size_t)l*D_,
            p_hin2, D_, D_, p_hin, p_mod + 2*D_);
        ln_mod_k<<<M_, 256>>>(p_hin2, p_mod, 3*D_, 4*D_, p_m2);
        gemm_k<EPI_GELU><<<dim3(16, 8), 256>>>(
            p_m2, mlp_w1 + (size_t)l*FF_*D_, mlp_b1 + (size_t)l*FF_,
            p_t, D_, FF_, nullptr, nullptr);
        float* dst = (l == NL_-1) ? (float*)d_out : p_h;
        gemm_k<EPI_GATERES><<<dim3(4, 8), 256>>>(
            p_t, mlp_w2 + (size_t)l*D_*FF_, mlp_b2 + (size_t)l*D_,
            dst, FF_, D_, p_hin2, p_mod + 5*D_);
    }
    (void)in_sizes; (void)n_in; (void)out_size;
}

// round 13
// speedup vs baseline: 1.5021x; 1.2621x over previous
#include <cuda_runtime.h>
#include <cuda_bf16.h>
#include <cstdint>
#include <cstddef>

#define B_ 2
#define L_ 512
#define D_ 512
#define H_ 16
#define P_ 128
#define NL_ 2
#define FF_ 2048
#define M_ (B_*L_)

// ------------------------- fp32 scratch -------------------------
__device__ float g_keep[M_];
__device__ float g_pfb[(size_t)B_*H_*L_*L_];
__device__ float g_hsum[(size_t)B_*L_*L_];
__device__ int   g_topk[M_*3];
__device__ float g_h[M_*D_];
__device__ float g_hin[M_*D_];
__device__ float g_mod[(size_t)M_*6*D_];
__device__ float g_qkv[M_*3*D_];
__device__ float g_s[(size_t)B_*H_*L_*L_];
__device__ float g_hin2[M_*D_];

// ------------------------- bf16 hi/lo weights -------------------------
__device__ __align__(16) __nv_bfloat16 wh_adaln[NL_*6*D_*D_], wl_adaln[NL_*6*D_*D_];
__device__ __align__(16) __nv_bfloat16 wh_qkv [NL_*3*D_*D_], wl_qkv [NL_*3*D_*D_];
__device__ __align__(16) __nv_bfloat16 wh_proj[NL_*D_*D_],   wl_proj[NL_*D_*D_];
__device__ __align__(16) __nv_bfloat16 wh_mlp1[NL_*FF_*D_],  wl_mlp1[NL_*FF_*D_];
__device__ __align__(16) __nv_bfloat16 wh_mlp2[NL_*D_*FF_],  wl_mlp2[NL_*D_*FF_];
__device__ __align__(16) __nv_bfloat16 wh_p2n1[P_*P_],       wl_p2n1[P_*P_];
__device__ __align__(16) __nv_bfloat16 wh_p2n2[D_*P_],       wl_p2n2[D_*P_];

// ------------------------- bf16 hi/lo activations -------------------------
__device__ __align__(16) __nv_bfloat16 fbh[M_*P_],  fbl[M_*P_];
__device__ __align__(16) __nv_bfloat16 tph[M_*P_],  tpl[M_*P_];
__device__ __align__(16) __nv_bfloat16 cbh[M_*D_],  cbl[M_*D_];
__device__ __align__(16) __nv_bfloat16 lbh[M_*D_],  lbl[M_*D_];
__device__ __align__(16) __nv_bfloat16 obh[M_*D_],  obl[M_*D_];
__device__ __align__(16) __nv_bfloat16 tbh[(size_t)M_*FF_], tbl[(size_t)M_*FF_];

__device__ __forceinline__ float siluf(float x){ return x * (1.f/(1.f + __expf(-x))); }
__device__ __forceinline__ float geluf(float x){
    return 0.5f*x*(1.f + tanhf(0.79788456080286536f*(x + 0.044715f*x*x*x)));
}
__device__ __forceinline__ void hisplit(float v, __nv_bfloat16& h, __nv_bfloat16& l){
    h = __float2bfloat16(v);
    l = __float2bfloat16(v - __bfloat162float(h));
}

#define MMA4(c, a, b0, b1) \
    asm volatile("mma.sync.aligned.m16n8k16.row.col.f32.bf16.bf16.f32 " \
        "{%0,%1,%2,%3}, {%4,%5,%6,%7}, {%8,%9}, {%0,%1,%2,%3};" \
        : "+f"((c)[0]), "+f"((c)[1]), "+f"((c)[2]), "+f"((c)[3]) \
        : "r"((a)[0]), "r"((a)[1]), "r"((a)[2]), "r"((a)[3]), "r"(b0), "r"(b1))

// ------------------------- weight fp32 -> bf16 hi/lo -------------------------
__global__ void __launch_bounds__(256) cvtw_k(const float* __restrict__ s,
                                              __nv_bfloat16* __restrict__ h,
                                              __nv_bfloat16* __restrict__ l, int n4) {
    int i = blockIdx.x*256 + threadIdx.x;
    if (i >= n4) return;
    float4 v = ((const float4*)s)[i];
    __nv_bfloat16 h0,h1,h2,h3,l0,l1,l2,l3;
    hisplit(v.x,h0,l0); hisplit(v.y,h1,l1); hisplit(v.z,h2,l2); hisplit(v.w,h3,l3);
    ((__nv_bfloat162*)h)[i*2]   = __halves2bfloat162(h0,h1);
    ((__nv_bfloat162*)h)[i*2+1] = __halves2bfloat162(h2,h3);
    ((__nv_bfloat162*)l)[i*2]   = __halves2bfloat162(l0,l1);
    ((__nv_bfloat162*)l)[i*2+1] = __halves2bfloat162(l2,l3);
}

// ------------------------- bf16 mma GEMM: C = A @ W^T (+bias) + epilogue -------------
#define EPI_PLAIN   0
#define EPI_SILU    1
#define EPI_XCOND   2
#define EPI_GELU    3
#define EPI_GATERES 4

template<int BM, int BN, int EPI, int OP>
__global__ void __launch_bounds__(256)
tgemm_k(const __nv_bfloat16* __restrict__ Ah, const __nv_bfloat16* __restrict__ Al,
        const __nv_bfloat16* __restrict__ Wh, const __nv_bfloat16* __restrict__ Wl,
        const float* __restrict__ bias,
        float* __restrict__ Cf, __nv_bfloat16* __restrict__ Ch, __nv_bfloat16* __restrict__ Cl,
        int K, int N,
        const float* __restrict__ aux, const float* __restrict__ gate)
{
    __shared__ __align__(16) __nv_bfloat16 sAh[BM][40];
    __shared__ __align__(16) __nv_bfloat16 sAl[BM][40];
    __shared__ __align__(16) __nv_bfloat16 sWh[BN][40];
    __shared__ __align__(16) __nv_bfloat16 sWl[BN][40];
    constexpr int MT = BM/32;   // warp covers BM/2 rows = MT*16
    constexpr int NT = BN/32;   // warp covers BN/4 cols = NT*8
    const int tid = threadIdx.x, wid = tid >> 5, lane = tid & 31;
    const int g = lane >> 2, tq = lane & 3;
    const int m0 = blockIdx.y*BM, n0 = blockIdx.x*BN;
    const int wm0 = (wid & 1)*(BM/2);
    const int wn0 = (wid >> 1)*(BN/4);

    float c[MT][NT][4];
    #pragma unroll
    for (int i = 0; i < MT; i++)
        #pragma unroll
        for (int j = 0; j < NT; j++)
            #pragma unroll
            for (int r = 0; r < 4; r++) c[i][j][r] = 0.f;

    for (int k0 = 0; k0 < K; k0 += 32) {
        #pragma unroll
        for (int u = tid; u < BM*4; u += 256) {
            int row = u >> 2, un = u & 3;
            size_t go = (size_t)(m0 + row)*K + k0 + un*8;
            *(uint4*)&sAh[row][un*8] = *(const uint4*)(Ah + go);
            *(uint4*)&sAl[row][un*8] = *(const uint4*)(Al + go);
        }
        #pragma unroll
        for (int u = tid; u < BN*4; u += 256) {
            int row = u >> 2, un = u & 3;
            size_t go = (size_t)(n0 + row)*K + k0 + un*8;
            *(uint4*)&sWh[row][un*8] = *(const uint4*)(Wh + go);
            *(uint4*)&sWl[row][un*8] = *(const uint4*)(Wl + go);
        }
        __syncthreads();
        #pragma unroll
        for (int ks = 0; ks < 32; ks += 16) {
            const int kc = ks + 2*tq;
            uint32_t aH[MT][4], aL[MT][4];
            #pragma unroll
            for (int mt = 0; mt < MT; mt++) {
                int r = wm0 + mt*16 + g;
                aH[mt][0] = *(const uint32_t*)&sAh[r  ][kc];
                aH[mt][1] = *(const uint32_t*)&sAh[r+8][kc];
                aH[mt][2] = *(const uint32_t*)&sAh[r  ][kc+8];
                aH[mt][3] = *(const uint32_t*)&sAh[r+8][kc+8];
                aL[mt][0] = *(const uint32_t*)&sAl[r  ][kc];
                aL[mt][1] = *(const uint32_t*)&sAl[r+8][kc];
                aL[mt][2] = *(const uint32_t*)&sAl[r  ][kc+8];
                aL[mt][3] = *(const uint32_t*)&sAl[r+8][kc+8];
            }
            #pragma unroll
            for (int nt = 0; nt < NT; nt++) {
                int rn = wn0 + nt*8 + g;
                uint32_t bH0 = *(const uint32_t*)&sWh[rn][kc];
                uint32_t bH1 = *(const uint32_t*)&sWh[rn][kc+8];
                uint32_t bL0 = *(const uint32_t*)&sWl[rn][kc];
                uint32_t bL1 = *(const uint32_t*)&sWl[rn][kc+8];
                #pragma unroll
                for (int mt = 0; mt < MT; mt++) {
                    MMA4(c[mt][nt], aH[mt], bH0, bH1);
                    MMA4(c[mt][nt], aH[mt], bL0, bL1);
                    MMA4(c[mt][nt], aL[mt], bH0, bH1);
                }
            }
        }
        __syncthreads();
    }

    // ---- epilogue ----
    #pragma unroll
    for (int mt = 0; mt < MT; mt++) {
        #pragma unroll
        for (int nt = 0; nt < NT; nt++) {
            int gn = n0 + wn0 + nt*8 + 2*tq;
            #pragma unroll
            for (int hf = 0; hf < 2; hf++) {
                int gm = m0 + wm0 + mt*16 + g + hf*8;
                float v0 = c[mt][nt][hf*2+0];
                float v1 = c[mt][nt][hf*2+1];
                if (bias) { v0 += bias[gn]; v1 += bias[gn+1]; }
                if (EPI == EPI_SILU) {
                    v0 = siluf(v0); v1 = siluf(v1);
                } else if (EPI == EPI_XCOND) {
                    int bb = gm >> 9, ll = gm & 511;
                    const float* xr = aux + ((size_t)(ll*B_ + bb))*D_ + gn;
                    v0 = siluf(xr[0] + v0); v1 = siluf(xr[1] + v1);
                } else if (EPI == EPI_GELU) {
                    v0 = geluf(v0); v1 = geluf(v1);
                } else if (EPI == EPI_GATERES) {
                    const float* ar = aux + (size_t)gm*D_ + gn;
                    const float* gr = gate + (size_t)gm*(6*D_) + gn;
                    v0 = ar[0] + gr[0]*v0; v1 = ar[1] + gr[1]*v1;
                }
                if (OP == 0) {
                    *(float2*)(Cf + (size_t)gm*N + gn) = make_float2(v0, v1);
                } else {
                    __nv_bfloat16 h0,h1,l0,l1;
                    hisplit(v0,h0,l0); hisplit(v1,h1,l1);
                    *(__nv_bfloat162*)(Ch + (size_t)gm*N + gn) = __halves2bfloat162(h0,h1);
                    *(__nv_bfloat162*)(Cl + (size_t)gm*N + gn) = __halves2bfloat162(l0,l1);
                }
            }
        }
    }
}

// ------------------------- mask decode -------------------------
__global__ void decode_mask_k(const unsigned int* __restrict__ raw) {
    int t = threadIdx.x;
    g_keep[t] = (raw[t] == 0u) ? 1.f : 0.f;
}

// ------------------------- pos embedding -------------------------
__global__ void __launch_bounds__(256) pos_emb_k(const float* __restrict__ pos,
                                                 const float* __restrict__ pw) {
    int i = blockIdx.x*256 + threadIdx.x;
    int row = i >> 9, d = i & 511;
    float v = pos[row*3+0]*pw[d*3+0] + pos[row*3+1]*pw[d*3+1] + pos[row*3+2]*pw[d*3+2];
    g_h[i] = g_keep[row] * v;
}

// ------------------------- pair bias + head-sum -------------------------
__global__ void __launch_bounds__(256) pfb_k(const float* __restrict__ pair,
                                             const float* __restrict__ pfbw) {
    __shared__ float sp[32][129];
    __shared__ float sw[16][128];
    __shared__ float shs[32];
    const int b = blockIdx.z, l = blockIdx.y, m0 = blockIdx.x * 32;
    const int tid = threadIdx.x;
    for (int i = tid; i < 512; i += 256) {
        float4 v = ((const float4*)pfbw)[i];
        int hh = i >> 5, p = (i & 31) * 4;
        sw[hh][p] = v.x; sw[hh][p+1] = v.y; sw[hh][p+2] = v.z; sw[hh][p+3] = v.w;
    }
    if (tid < 32) shs[tid] = 0.f;
    const float* src = pair + (((size_t)(b * L_ + l)) * L_ + m0) * P_;
    for (int i = tid; i < 1024; i += 256) {
        float4 v = ((const float4*)src)[i];
        int mm = i >> 5, p = (i & 31) * 4;
        sp[mm][p]   = siluf(v.x); sp[mm][p+1] = siluf(v.y);
        sp[mm][p+2] = siluf(v.z); sp[mm][p+3] = siluf(v.w);
    }
    __syncthreads();
    const int m = tid & 31, h0 = (tid >> 5) * 2;
    float a0 = 0.f, a1 = 0.f;
    #pragma unroll 16
    for (int p = 0; p < 128; p++) {
        float v = sp[m][p];
        a0 = fmaf(v, sw[h0][p], a0);
        a1 = fmaf(v, sw[h0+1][p], a1);
    }
    size_t base = ((size_t)((b*H_ + h0) * L_ + l)) * L_ + m0 + m;
    g_pfb[base] = a0;
    g_pfb[base + (size_t)L_*L_] = a1;
    atomicAdd(&shs[m], a0 + a1);
    __syncthreads();
    if (tid < 32)
        g_hsum[((size_t)(b*L_ + l))*L_ + m0 + tid] = shs[tid];
}

// ------------------------- top-3 rows per (b, column m) -------------------------
__global__ void __launch_bounds__(256) topk_k() {
    const int warp = threadIdx.x >> 5, lane = threadIdx.x & 31;
    const int bm = blockIdx.x * 8 + warp;
    const int b = bm >> 9, m = bm & 511;
    float lv[3] = {-3.4e38f, -3.4e38f, -3.4e38f};
    int   li[3] = {0x7fffffff, 0x7fffffff, 0x7fffffff};
    for (int l = lane; l < L_; l += 32) {
        float s = g_hsum[((size_t)(b*L_ + l))*L_ + m];
        if (s > lv[0])      { lv[2]=lv[1]; li[2]=li[1]; lv[1]=lv[0]; li[1]=li[0]; lv[0]=s; li[0]=l; }
        else if (s > lv[1]) { lv[2]=lv[1]; li[2]=li[1]; lv[1]=s; li[1]=l; }
        else if (s > lv[2]) { lv[2]=s; li[2]=l; }
    }
    int ptr = 0;
    for (int r = 0; r < 3; r++) {
        float bv = (ptr < 3) ? lv[ptr] : -3.4e38f;
        int   bi = (ptr < 3) ? li[ptr] : 0x7fffffff;
        int   bl = lane;
        #pragma unroll
        for (int o = 16; o; o >>= 1) {
            float ov = __shfl_down_sync(0xffffffffu, bv, o);
            int   oi = __shfl_down_sync(0xffffffffu, bi, o);
            int   ol = __shfl_down_sync(0xffffffffu, bl, o);
            if (ov > bv || (ov == bv && oi < bi)) { bv = ov; bi = oi; bl = ol; }
        }
        bi = __shfl_sync(0xffffffffu, bi, 0);
        bl = __shfl_sync(0xffffffffu, bl, 0);
        if (lane == bl) ptr++;
        if (lane == 0) g_topk[bm*3 + r] = bi;
    }
}

// ------------------------- f2n gather -> bf16 pair -------------------------
__global__ void __launch_bounds__(128) f2n_k(const float* __restrict__ pair) {
    const int bm = blockIdx.x;
    const int b = bm >> 9, m = bm & 511;
    const int p = threadIdx.x;
    float acc = 0.f;
    #pragma unroll
    for (int t = 0; t < 3; t++) {
        int l = g_topk[bm*3 + t];
        acc += g_keep[b*L_ + l] * pair[(((size_t)(b*L_ + l))*L_ + m)*P_ + p];
    }
    acc *= g_keep[bm] * (1.f/3.f);
    __nv_bfloat16 h, l2;
    hisplit(acc, h, l2);
    fbh[bm*P_ + p] = h;
    fbl[bm*P_ + p] = l2;
}

// ------------------------- hin = h + time_emb -------------------------
__global__ void __launch_bounds__(256) add_te_k(const float* __restrict__ te) {
    int i = blockIdx.x*256 + threadIdx.x;
    int row = i >> 9;
    int b = row >> 9;
    g_hin[i] = g_h[i] + te[(b << 9) + (i & 511)];
}

// ------------------------- LayerNorm + adaLN -> bf16 pair -------------------------
__global__ void __launch_bounds__(256) ln_mod_k(const float* __restrict__ in,
                                                const float* __restrict__ mod,
                                                int sh_off, int sc_off,
                                                __nv_bfloat16* __restrict__ outh,
                                                __nv_bfloat16* __restrict__ outl) {
    const int row = blockIdx.x;
    const float* xr = in + (size_t)row*D_;
    const int t = threadIdx.x;
    float v0 = xr[t], v1 = xr[t+256];
    float s = v0 + v1, q = v0*v0 + v1*v1;
    __shared__ float ss[8], sq[8];
    int lane = t & 31, w = t >> 5;
    #pragma unroll
    for (int o = 16; o; o >>= 1) {
        s += __shfl_down_sync(0xffffffffu, s, o);
        q += __shfl_down_sync(0xffffffffu, q, o);
    }
    if (!lane) { ss[w] = s; sq[w] = q; }
    __syncthreads();
    if (t == 0) {
        float S = 0.f, Q = 0.f;
        #pragma unroll
        for (int i = 0; i < 8; i++) { S += ss[i]; Q += sq[i]; }
        ss[0] = S; sq[0] = Q;
    }
    __syncthreads();
    float mean = ss[0] * (1.f/512.f);
    float var  = sq[0] * (1.f/512.f) - mean*mean;
    float inv  = rsqrtf(var + 1e-5f);
    const float* mrow = mod + (size_t)row*(6*D_);
    float o0 = (v0-mean)*inv*(1.f + mrow[sc_off + t])     + mrow[sh_off + t];
    float o1 = (v1-mean)*inv*(1.f + mrow[sc_off + t+256]) + mrow[sh_off + t+256];
    __nv_bfloat16 h0,l0,h1,l1;
    hisplit(o0,h0,l0); hisplit(o1,h1,l1);
    outh[(size_t)row*D_ + t]       = h0;
    outl[(size_t)row*D_ + t]       = l0;
    outh[(size_t)row*D_ + t + 256] = h1;
    outl[(size_t)row*D_ + t + 256] = l1;
}

// ------------------------- attention scores -------------------------
__global__ void __launch_bounds__(256) attn_scores_k() {
    __shared__ float Qs[64][33];
    __shared__ float Ks[64][33];
    const int bh = blockIdx.z, b = bh >> 4, h = bh & 15;
    const int l0 = blockIdx.y * 64, m0 = blockIdx.x * 64;
    const int tid = threadIdx.x;
    const float* qbase = g_qkv + ((size_t)(b*L_ + l0)) * 1536 + h * 32;
    const float* kbase = g_qkv + ((size_t)(b*L_ + m0)) * 1536 + 512 + h * 32;
    #pragma unroll
    for (int i = tid; i < 512; i += 256) {
        int r = i >> 3, c4 = (i & 7) * 4;
        float4 q4 = *(const float4*)(qbase + (size_t)r * 1536 + c4);
        Qs[r][c4] = q4.x; Qs[r][c4+1] = q4.y; Qs[r][c4+2] = q4.z; Qs[r][c4+3] = q4.w;
        float4 k4 = *(const float4*)(kbase + (size_t)r * 1536 + c4);
        Ks[r][c4] = k4.x; Ks[r][c4+1] = k4.y; Ks[r][c4+2] = k4.z; Ks[r][c4+3] = k4.w;
    }
    __syncthreads();
    const int tx = tid & 15, ty = tid >> 4;
    float acc[4][4] = {};
    #pragma unroll
    for (int k = 0; k < 32; k++) {
        float a[4], bb[4];
        #pragma unroll
        for (int i = 0; i < 4; i++) a[i] = Qs[ty*4 + i][k];
        #pragma unroll
        for (int j = 0; j < 4; j++) bb[j] = Ks[tx*4 + j][k];
        #pragma unroll
        for (int i = 0; i < 4; i++)
            #pragma unroll
            for (int j = 0; j < 4; j++)
                acc[i][j] = fmaf(a[i], bb[j], acc[i][j]);
    }
    const float scale = 0.17677669529663687f;
    #pragma unroll
    for (int i = 0; i < 4; i++) {
        int l = l0 + ty*4 + i;
        size_t srow = ((size_t)(bh*L_ + l)) * L_;
        #pragma unroll
        for (int j = 0; j < 4; j++) {
            int m = m0 + tx*4 + j;
            float v = acc[i][j] * scale + g_pfb[srow + m];
            if (g_keep[b*L_ + m] == 0.f) v = -1e9f;
            g_s[srow + m] = v;
        }
    }
}

// ------------------------- softmax -------------------------
__global__ void __launch_bounds__(256) softmax_k() {
    const size_t base = (size_t)blockIdx.x * 512;
    const int t = threadIdx.x;
    float v0 = g_s[base + t], v1 = g_s[base + t + 256];
    __shared__ float red[8];
    __shared__ float red2[8];
    int lane = t & 31, w = t >> 5;
    float m = fmaxf(v0, v1);
    #pragma unroll
    for (int o = 16; o; o >>= 1) m = fmaxf(m, __shfl_down_sync(0xffffffffu, m, o));
    if (!lane) red[w] = m;
    __syncthreads();
    if (t == 0) {
        float M = red[0];
        #pragma unroll
        for (int i = 1; i < 8; i++) M = fmaxf(M, red[i]);
        red[0] = M;
    }
    __syncthreads();
    float M = red[0];
    float e0 = __expf(v0 - M), e1 = __expf(v1 - M);
    float s = e0 + e1;
    #pragma unroll
    for (int o = 16; o; o >>= 1) s += __shfl_down_sync(0xffffffffu, s, o);
    if (!lane) red2[w] = s;
    __syncthreads();
    if (t == 0) {
        float S = 0.f;
        #pragma unroll
        for (int i = 0; i < 8; i++) S += red2[i];
        red2[0] = 1.f / S;
    }
    __syncthreads();
    float inv = red2[0];
    g_s[base + t] = e0 * inv;
    g_s[base + t + 256] = e1 * inv;
}

// ------------------------- O = P @ V -> bf16 pair -------------------------
__global__ void __launch_bounds__(256) attn_o_k() {
    __shared__ float Ps[64][65];
    __shared__ float Vs[64][33];
    const int bh = blockIdx.y, b = bh >> 4, h = bh & 15;
    const int l0 = blockIdx.x * 64;
    const int tid = threadIdx.x;
    const int tx = tid & 31, ty = tid >> 5;
    float acc[8] = {};
    for (int m0 = 0; m0 < 512; m0 += 64) {
        #pragma unroll
        for (int i = tid; i < 1024; i += 256) {
            int r = i >> 4, c4 = (i & 15) * 4;
            float4 p4 = *(const float4*)(g_s + ((size_t)(bh*L_ + l0 + r))*L_ + m0 + c4);
            Ps[r][c4] = p4.x; Ps[r][c4+1] = p4.y; Ps[r][c4+2] = p4.z; Ps[r][c4+3] = p4.w;
        }
        #pragma unroll
        for (int i = tid; i < 512; i += 256) {
            int r = i >> 3, c4 = (i & 7) * 4;
            float4 v4 = *(const float4*)(g_qkv + ((size_t)(b*L_ + m0 + r))*1536 + 1024 + h*32 + c4);
            Vs[r][c4] = v4.x; Vs[r][c4+1] = v4.y; Vs[r][c4+2] = v4.z; Vs[r][c4+3] = v4.w;
        }
        __syncthreads();
        #pragma unroll 16
        for (int m = 0; m < 64; m++) {
            float v = Vs[m][tx];
            #pragma unroll
            for (int i = 0; i < 8; i++)
                acc[i] = fmaf(Ps[ty + 8*i][m], v, acc[i]);
        }
        __syncthreads();
    }
    #pragma unroll
    for (int i = 0; i < 8; i++) {
        int l = l0 + ty + 8*i;
        __nv_bfloat16 hb, lb;
        hisplit(acc[i], hb, lb);
        obh[((size_t)(b*L_ + l))*D_ + h*32 + tx] = hb;
        obl[((size_t)(b*L_ + l))*D_ + h*32 + tx] = lb;
    }
}

// ------------------------- host launch -------------------------
extern "C" void kernel_launch(void* const* d_in, const int* in_sizes, int n_in,
                              void* d_out, int out_size) {
    const float* x        = (const float*)d_in[0];
    const float* pos      = (const float*)d_in[1];
    const float* time_emb = (const float*)d_in[2];
    const float* pair     = (const float*)d_in[3];
    const float* pos_w    = (const float*)d_in[4];
    const float* pfb_w    = (const float*)d_in[5];
    const float* p2n_w1   = (const float*)d_in[6];
    const float* p2n_w2   = (const float*)d_in[7];
    const float* adaln_w  = (const float*)d_in[8];
    const float* adaln_b  = (const float*)d_in[9];
    const float* qkv_w    = (const float*)d_in[10];
    const float* qkv_b    = (const float*)d_in[11];
    const float* proj_w   = (const float*)d_in[12];
    const float* proj_b   = (const float*)d_in[13];
    const float* mlp_w1   = (const float*)d_in[14];
    const float* mlp_b1   = (const float*)d_in[15];
    const float* mlp_w2   = (const float*)d_in[16];
    const float* mlp_b2   = (const float*)d_in[17];
    const unsigned int* mask = (const unsigned int*)d_in[18];

    float *p_h, *p_hin, *p_mod, *p_hin2, *p_qkv;
    cudaGetSymbolAddress((void**)&p_h,    g_h);
    cudaGetSymbolAddress((void**)&p_hin,  g_hin);
    cudaGetSymbolAddress((void**)&p_mod,  g_mod);
    cudaGetSymbolAddress((void**)&p_hin2, g_hin2);
    cudaGetSymbolAddress((void**)&p_qkv,  g_qkv);

    __nv_bfloat16 *pwh_ad, *pwl_ad, *pwh_qk, *pwl_qk, *pwh_pr, *pwl_pr;
    __nv_bfloat16 *pwh_m1, *pwl_m1, *pwh_m2, *pwl_m2, *pwh_p1, *pwl_p1, *pwh_p2, *pwl_p2;
    __nv_bfloat16 *pfbh, *pfbl, *ptph, *ptpl, *pcbh, *pcbl, *plbh, *plbl, *pobh, *pobl, *ptbh, *ptbl;
    cudaGetSymbolAddress((void**)&pwh_ad, wh_adaln); cudaGetSymbolAddress((void**)&pwl_ad, wl_adaln);
    cudaGetSymbolAddress((void**)&pwh_qk, wh_qkv);   cudaGetSymbolAddress((void**)&pwl_qk, wl_qkv);
    cudaGetSymbolAddress((void**)&pwh_pr, wh_proj);  cudaGetSymbolAddress((void**)&pwl_pr, wl_proj);
    cudaGetSymbolAddress((void**)&pwh_m1, wh_mlp1);  cudaGetSymbolAddress((void**)&pwl_m1, wl_mlp1);
    cudaGetSymbolAddress((void**)&pwh_m2, wh_mlp2);  cudaGetSymbolAddress((void**)&pwl_m2, wl_mlp2);
    cudaGetSymbolAddress((void**)&pwh_p1, wh_p2n1);  cudaGetSymbolAddress((void**)&pwl_p1, wl_p2n1);
    cudaGetSymbolAddress((void**)&pwh_p2, wh_p2n2);  cudaGetSymbolAddress((void**)&pwl_p2, wl_p2n2);
    cudaGetSymbolAddress((void**)&pfbh, fbh); cudaGetSymbolAddress((void**)&pfbl, fbl);
    cudaGetSymbolAddress((void**)&ptph, tph); cudaGetSymbolAddress((void**)&ptpl, tpl);
    cudaGetSymbolAddress((void**)&pcbh, cbh); cudaGetSymbolAddress((void**)&pcbl, cbl);
    cudaGetSymbolAddress((void**)&plbh, lbh); cudaGetSymbolAddress((void**)&plbl, lbl);
    cudaGetSymbolAddress((void**)&pobh, obh); cudaGetSymbolAddress((void**)&pobl, obl);
    cudaGetSymbolAddress((void**)&ptbh, tbh); cudaGetSymbolAddress((void**)&ptbl, tbl);

    // weight conversions (recomputed each call; deterministic)
    cvtw_k<<<(NL_*6*D_*D_/4 + 255)/256, 256>>>(adaln_w, pwh_ad, pwl_ad, NL_*6*D_*D_/4);
    cvtw_k<<<(NL_*3*D_*D_/4 + 255)/256, 256>>>(qkv_w,   pwh_qk, pwl_qk, NL_*3*D_*D_/4);
    cvtw_k<<<(NL_*D_*D_/4   + 255)/256, 256>>>(proj_w,  pwh_pr, pwl_pr, NL_*D_*D_/4);
    cvtw_k<<<(NL_*FF_*D_/4  + 255)/256, 256>>>(mlp_w1,  pwh_m1, pwl_m1, NL_*FF_*D_/4);
    cvtw_k<<<(NL_*D_*FF_/4  + 255)/256, 256>>>(mlp_w2,  pwh_m2, pwl_m2, NL_*D_*FF_/4);
    cvtw_k<<<(P_*P_/4 + 255)/256, 256>>>(p2n_w1, pwh_p1, pwl_p1, P_*P_/4);
    cvtw_k<<<(D_*P_/4 + 255)/256, 256>>>(p2n_w2, pwh_p2, pwl_p2, D_*P_/4);

    decode_mask_k<<<1, 1024>>>(mask);
    pos_emb_k<<<(M_*D_)/256, 256>>>(pos, pos_w);
    pfb_k<<<dim3(L_/32, L_, B_), 256>>>(pair, pfb_w);
    topk_k<<<M_/8, 256>>>();
    f2n_k<<<M_, 128>>>(pair);

    tgemm_k<64,64,EPI_SILU,1><<<dim3(2, 16), 256>>>(
        pfbh, pfbl, pwh_p1, pwl_p1, nullptr, nullptr, ptph, ptpl, P_, P_, nullptr, nullptr);
    tgemm_k<64,64,EPI_XCOND,1><<<dim3(8, 16), 256>>>(
        ptph, ptpl, pwh_p2, pwl_p2, nullptr, nullptr, pcbh, pcbl, P_, D_, x, nullptr);

    for (int l = 0; l < NL_; l++) {
        add_te_k<<<(M_*D_)/256, 256>>>(time_emb);
        tgemm_k<128,128,EPI_PLAIN,0><<<dim3(24, 8), 256>>>(
            pcbh, pcbl, pwh_ad + (size_t)l*6*D_*D_, pwl_ad + (size_t)l*6*D_*D_,
            adaln_b + (size_t)l*6*D_, p_mod, nullptr, nullptr, D_, 6*D_, nullptr, nullptr);
        ln_mod_k<<<M_, 256>>>(p_hin, p_mod, 0, D_, plbh, plbl);
        tgemm_k<128,128,EPI_PLAIN,0><<<dim3(12, 8), 256>>>(
            plbh, plbl, pwh_qk + (size_t)l*3*D_*D_, pwl_qk + (size_t)l*3*D_*D_,
            qkv_b + (size_t)l*3*D_, p_qkv, nullptr, nullptr, D_, 3*D_, nullptr, nullptr);
        attn_scores_k<<<dim3(L_/64, L_/64, B_*H_), 256>>>();
        softmax_k<<<B_*H_*L_, 256>>>();
        attn_o_k<<<dim3(L_/64, B_*H_), 256>>>();
        tgemm_k<64,64,EPI_GATERES,0><<<dim3(8, 16), 256>>>(
            pobh, pobl, pwh_pr + (size_t)l*D_*D_, pwl_pr + (size_t)l*D_*D_,
            proj_b + (size_t)l*D_, p_hin2, nullptr, nullptr, D_, D_, p_hin, p_mod + 2*D_);
        ln_mod_k<<<M_, 256>>>(p_hin2, p_mod, 3*D_, 4*D_, plbh, plbl);
        tgemm_k<128,128,EPI_GELU,1><<<dim3(16, 8), 256>>>(
            plbh, plbl, pwh_m1 + (size_t)l*FF_*D_, pwl_m1 + (size_t)l*FF_*D_,
            mlp_b1 + (size_t)l*FF_, nullptr, ptbh, ptbl, D_, FF_, nullptr, nullptr);
        float* dst = (l == NL_-1) ? (float*)d_out : p_h;
        tgemm_k<64,64,EPI_GATERES,0><<<dim3(8, 16), 256>>>(
            ptbh, ptbl, pwh_m2 + (size_t)l*D_*FF_, pwl_m2 + (size_t)l*D_*FF_,
            mlp_b2 + (size_t)l*D_, dst, nullptr, nullptr, FF_, D_, p_hin2, p_mod + 5*D_);
    }
    (void)in_sizes; (void)n_in; (void)out_size;
}